// round 1
// baseline (speedup 1.0000x reference)
#include <cuda_runtime.h>
#include <cuda_bf16.h>
#include <cstdint>

#define N_NODES 100000
#define N_EDGES 3200000
#define IN_K    512     // IN_DIM * N_SEQ
#define HID1    256
#define HID2    128
#define ENDD    64

// ---------------- scratch (device globals; no allocation allowed) ----------------
__device__ int   g_deg_out[N_NODES];
__device__ int   g_deg_in[N_NODES];
__device__ int   g_fill[N_NODES];
__device__ float g_rso[N_NODES];
__device__ float g_rsi[N_NODES];
__device__ int   g_rowptr[N_NODES + 1];
__device__ int   g_bsums[512];
__device__ int   g_colidx[N_EDGES];
__device__ float g_Z1[(size_t)N_NODES * HID1];   // 102 MB
__device__ float g_A1[(size_t)N_NODES * HID1];   // 102 MB
__device__ float g_Z2[(size_t)N_NODES * ENDD];   // 25.6 MB
__device__ float g_W2f[HID1 * ENDD];             // W2 @ Wo1 (256x64)
__device__ float g_bh[ENDD];                     // b2 @ Wo1 + bo1

// ---------------- preprocessing kernels ----------------
__global__ void k_zero()
{
    int i = blockIdx.x * blockDim.x + threadIdx.x;
    if (i < N_NODES) { g_deg_out[i] = 0; g_deg_in[i] = 0; g_fill[i] = 0; }
}

__global__ void k_degree(const int* __restrict__ src, const int* __restrict__ dst)
{
    int e = blockIdx.x * blockDim.x + threadIdx.x;
    if (e < N_EDGES) {
        atomicAdd(&g_deg_out[src[e]], 1);
        atomicAdd(&g_deg_in[dst[e]], 1);
    }
}

__global__ void k_rsqrt()
{
    int i = blockIdx.x * blockDim.x + threadIdx.x;
    if (i < N_NODES) {
        g_rso[i] = rsqrtf((float)max(g_deg_out[i], 1));
        g_rsi[i] = rsqrtf((float)max(g_deg_in[i], 1));
    }
}

// exclusive scan of g_deg_in -> g_rowptr  (3 kernels)
__global__ void k_scan1()
{
    __shared__ int s[256];
    int t = threadIdx.x;
    int i = blockIdx.x * 256 + t;
    int v = (i < N_NODES) ? g_deg_in[i] : 0;
    s[t] = v; __syncthreads();
    #pragma unroll
    for (int off = 1; off < 256; off <<= 1) {
        int u = (t >= off) ? s[t - off] : 0;
        __syncthreads();
        s[t] += u;
        __syncthreads();
    }
    if (i < N_NODES) g_rowptr[i] = s[t] - v;   // exclusive within block
    if (t == 255) g_bsums[blockIdx.x] = s[255];
}

__global__ void k_scan2()
{
    __shared__ int s[512];
    const int nb = (N_NODES + 255) / 256;   // 391
    int t = threadIdx.x;
    int v = (t < nb) ? g_bsums[t] : 0;
    s[t] = v; __syncthreads();
    #pragma unroll
    for (int off = 1; off < 512; off <<= 1) {
        int u = (t >= off) ? s[t - off] : 0;
        __syncthreads();
        s[t] += u;
        __syncthreads();
    }
    if (t < nb) g_bsums[t] = s[t] - v;      // exclusive block offsets
}

__global__ void k_scan3()
{
    int i = blockIdx.x * blockDim.x + threadIdx.x;
    if (i < N_NODES) g_rowptr[i] += g_bsums[i >> 8];
    if (i == 0) g_rowptr[N_NODES] = N_EDGES;
}

__global__ void k_fill(const int* __restrict__ src, const int* __restrict__ dst)
{
    int e = blockIdx.x * blockDim.x + threadIdx.x;
    if (e < N_EDGES) {
        int d = dst[e];
        int p = g_rowptr[d] + atomicAdd(&g_fill[d], 1);
        g_colidx[p] = src[e];
    }
}

// W2f = W2 @ Wo1 (256x128 @ 128x64); bh = b2 @ Wo1 + bo1
__global__ void k_fuse(const float* __restrict__ W2, const float* __restrict__ Wo1,
                       const float* __restrict__ b2, const float* __restrict__ bo1)
{
    int j = threadIdx.x;   // 0..63
    int k = blockIdx.x;    // 0..256 (257 blocks; last one = bias)
    if (k < HID1) {
        float s = 0.f;
        #pragma unroll 8
        for (int m = 0; m < HID2; m++) s += W2[k * HID2 + m] * Wo1[m * ENDD + j];
        g_W2f[k * ENDD + j] = s;
    } else {
        float s = bo1[j];
        #pragma unroll 8
        for (int m = 0; m < HID2; m++) s += b2[m] * Wo1[m * ENDD + j];
        g_bh[j] = s;
    }
}

// ---------------- register-blocked SGEMM with per-row output scale ----------------
// C[row, col] = rowscale[row] * sum_k A[row,k] * B[k,col]
template<int BM, int BN, int BK, int TM, int TN>
__global__ void sgemm_rowscale(const float* __restrict__ A, const float* __restrict__ B,
                               const float* __restrict__ rowscale, float* __restrict__ C,
                               int M, int N, int K)
{
    constexpr int THREADS = (BM / TM) * (BN / TN);
    __shared__ float As[BK][BM];
    __shared__ float Bs[BK][BN];

    const int tid = threadIdx.x;
    const int tx  = tid % (BN / TN);
    const int ty  = tid / (BN / TN);
    const int blockRow = blockIdx.y * BM;
    const int blockCol = blockIdx.x * BN;

    constexpr int A_PER = (BM * BK / 4) / THREADS;
    constexpr int B_PER = (BK * BN / 4) / THREADS;

    float acc[TM][TN];
    #pragma unroll
    for (int i = 0; i < TM; i++)
        #pragma unroll
        for (int j = 0; j < TN; j++) acc[i][j] = 0.f;

    for (int k0 = 0; k0 < K; k0 += BK) {
        // A tile: BM x BK, float4 along K, store transposed
        #pragma unroll
        for (int i = 0; i < A_PER; i++) {
            int id = tid + i * THREADS;
            int r  = id / (BK / 4);
            int c4 = id % (BK / 4);
            int grow = blockRow + r;
            float4 v = make_float4(0.f, 0.f, 0.f, 0.f);
            if (grow < M) v = *(const float4*)(A + (size_t)grow * K + k0 + c4 * 4);
            As[c4 * 4 + 0][r] = v.x;
            As[c4 * 4 + 1][r] = v.y;
            As[c4 * 4 + 2][r] = v.z;
            As[c4 * 4 + 3][r] = v.w;
        }
        // B tile: BK x BN, float4 along N
        #pragma unroll
        for (int i = 0; i < B_PER; i++) {
            int id = tid + i * THREADS;
            int r  = id / (BN / 4);
            int c4 = id % (BN / 4);
            *(float4*)&Bs[r][c4 * 4] =
                *(const float4*)(B + (size_t)(k0 + r) * N + blockCol + c4 * 4);
        }
        __syncthreads();

        #pragma unroll
        for (int k = 0; k < BK; k++) {
            float ra[TM], rb[TN];
            #pragma unroll
            for (int i = 0; i < TM; i += 4) {
                float4 t = *(const float4*)&As[k][ty * TM + i];
                ra[i] = t.x; ra[i + 1] = t.y; ra[i + 2] = t.z; ra[i + 3] = t.w;
            }
            #pragma unroll
            for (int j = 0; j < TN; j += 4) {
                float4 t = *(const float4*)&Bs[k][tx * TN + j];
                rb[j] = t.x; rb[j + 1] = t.y; rb[j + 2] = t.z; rb[j + 3] = t.w;
            }
            #pragma unroll
            for (int i = 0; i < TM; i++)
                #pragma unroll
                for (int j = 0; j < TN; j++)
                    acc[i][j] += ra[i] * rb[j];
        }
        __syncthreads();
    }

    #pragma unroll
    for (int i = 0; i < TM; i++) {
        int grow = blockRow + ty * TM + i;
        if (grow >= M) continue;
        float s = rowscale[grow];
        #pragma unroll
        for (int j = 0; j < TN; j += 4) {
            float4 v;
            v.x = acc[i][j + 0] * s;
            v.y = acc[i][j + 1] * s;
            v.z = acc[i][j + 2] * s;
            v.w = acc[i][j + 3] * s;
            *(float4*)(C + (size_t)grow * N + blockCol + tx * TN + j) = v;
        }
    }
}

// ---------------- aggregation layer 1 (dim 256) + relu ----------------
// block = 256 threads = 4 groups of 64 lanes; group handles one dst node; lane owns a float4
__global__ void k_agg1_relu(const float* __restrict__ b1)
{
    int grp  = threadIdx.x >> 6;
    int lane = threadIdx.x & 63;
    int n = blockIdx.x * 4 + grp;
    if (n >= N_NODES) return;
    int beg = g_rowptr[n], end = g_rowptr[n + 1];

    float4 acc = make_float4(0.f, 0.f, 0.f, 0.f);
    int e = beg;
    for (; e + 4 <= end; e += 4) {
        int c0 = g_colidx[e], c1 = g_colidx[e + 1], c2 = g_colidx[e + 2], c3 = g_colidx[e + 3];
        float4 v0 = *(const float4*)(g_Z1 + (size_t)c0 * HID1 + lane * 4);
        float4 v1 = *(const float4*)(g_Z1 + (size_t)c1 * HID1 + lane * 4);
        float4 v2 = *(const float4*)(g_Z1 + (size_t)c2 * HID1 + lane * 4);
        float4 v3 = *(const float4*)(g_Z1 + (size_t)c3 * HID1 + lane * 4);
        acc.x += (v0.x + v1.x) + (v2.x + v3.x);
        acc.y += (v0.y + v1.y) + (v2.y + v3.y);
        acc.z += (v0.z + v1.z) + (v2.z + v3.z);
        acc.w += (v0.w + v1.w) + (v2.w + v3.w);
    }
    for (; e < end; e++) {
        int c = g_colidx[e];
        float4 v = *(const float4*)(g_Z1 + (size_t)c * HID1 + lane * 4);
        acc.x += v.x; acc.y += v.y; acc.z += v.z; acc.w += v.w;
    }
    float s = g_rsi[n];
    float4 bb = *(const float4*)(b1 + lane * 4);
    float4 o;
    o.x = fmaxf(fmaf(s, acc.x, bb.x), 0.f);
    o.y = fmaxf(fmaf(s, acc.y, bb.y), 0.f);
    o.z = fmaxf(fmaf(s, acc.z, bb.z), 0.f);
    o.w = fmaxf(fmaf(s, acc.w, bb.w), 0.f);
    *(float4*)(g_A1 + (size_t)n * HID1 + lane * 4) = o;
}

// ---------------- aggregation layer 2 (dim 64) + fused head ----------------
// block = 256 threads = 8 warps; warp handles one dst node; lane owns a float2
__global__ void k_agg2_head(const float* __restrict__ Wo2, const float* __restrict__ bo2,
                            float* __restrict__ out)
{
    int w    = threadIdx.x >> 5;
    int lane = threadIdx.x & 31;
    int n = blockIdx.x * 8 + w;
    if (n >= N_NODES) return;
    int beg = g_rowptr[n], end = g_rowptr[n + 1];

    float2 acc = make_float2(0.f, 0.f);
    int e = beg;
    for (; e + 4 <= end; e += 4) {
        int c0 = g_colidx[e], c1 = g_colidx[e + 1], c2 = g_colidx[e + 2], c3 = g_colidx[e + 3];
        float2 v0 = *(const float2*)(g_Z2 + (size_t)c0 * ENDD + lane * 2);
        float2 v1 = *(const float2*)(g_Z2 + (size_t)c1 * ENDD + lane * 2);
        float2 v2 = *(const float2*)(g_Z2 + (size_t)c2 * ENDD + lane * 2);
        float2 v3 = *(const float2*)(g_Z2 + (size_t)c3 * ENDD + lane * 2);
        acc.x += (v0.x + v1.x) + (v2.x + v3.x);
        acc.y += (v0.y + v1.y) + (v2.y + v3.y);
    }
    for (; e < end; e++) {
        int c = g_colidx[e];
        float2 v = *(const float2*)(g_Z2 + (size_t)c * ENDD + lane * 2);
        acc.x += v.x; acc.y += v.y;
    }
    float s  = g_rsi[n];
    float t0 = fmaxf(fmaf(s, acc.x, g_bh[lane * 2 + 0]), 0.f);
    float t1 = fmaxf(fmaf(s, acc.y, g_bh[lane * 2 + 1]), 0.f);
    float p  = t0 * Wo2[lane * 2] + t1 * Wo2[lane * 2 + 1];
    #pragma unroll
    for (int off = 16; off; off >>= 1) p += __shfl_down_sync(0xffffffffu, p, off);
    if (lane == 0) out[n] = p + bo2[0];
}

// ---------------- launch ----------------
extern "C" void kernel_launch(void* const* d_in, const int* in_sizes, int n_in,
                              void* d_out, int out_size)
{
    const float* features = (const float*)d_in[0];   // [100000, 64, 8] == [100000, 512]
    const int*   src      = (const int*)d_in[1];
    const int*   dst      = (const int*)d_in[2];
    const float* W1       = (const float*)d_in[3];   // [512, 256]
    const float* b1       = (const float*)d_in[4];
    const float* W2       = (const float*)d_in[5];   // [256, 128]
    const float* b2       = (const float*)d_in[6];
    const float* Wo1      = (const float*)d_in[7];   // [128, 64]
    const float* bo1      = (const float*)d_in[8];
    const float* Wo2      = (const float*)d_in[9];   // [64, 1]
    const float* bo2      = (const float*)d_in[10];
    float* out = (float*)d_out;

    const int nodeBlocks = (N_NODES + 255) / 256;    // 391
    const int edgeBlocks = (N_EDGES + 255) / 256;    // 12500

    // preprocessing: degrees, rsqrt, CSR-by-dst
    k_zero<<<nodeBlocks, 256>>>();
    k_degree<<<edgeBlocks, 256>>>(src, dst);
    k_rsqrt<<<nodeBlocks, 256>>>();
    k_scan1<<<nodeBlocks, 256>>>();
    k_scan2<<<1, 512>>>();
    k_scan3<<<nodeBlocks, 256>>>();
    k_fill<<<edgeBlocks, 256>>>(src, dst);
    k_fuse<<<HID1 + 1, ENDD>>>(W2, Wo1, b2, bo1);

    // layer 1: Z1 = rs_out * (X @ W1)  [100k, 256]
    {
        dim3 grid(HID1 / 128, (N_NODES + 127) / 128);
        float* rso; cudaGetSymbolAddress((void**)&rso, g_rso);
        float* z1;  cudaGetSymbolAddress((void**)&z1, g_Z1);
        sgemm_rowscale<128, 128, 16, 8, 8><<<grid, 256>>>(features, W1, rso, z1,
                                                          N_NODES, HID1, IN_K);
    }
    // A1 = relu(rs_in * agg(Z1) + b1)
    k_agg1_relu<<<N_NODES / 4, 256>>>(b1);

    // layer 2 (folded with head Linear1): Z2 = rs_out * (A1 @ (W2@Wo1))  [100k, 64]
    {
        dim3 grid(ENDD / 64, (N_NODES + 127) / 128);
        float* rso; cudaGetSymbolAddress((void**)&rso, g_rso);
        float* a1;  cudaGetSymbolAddress((void**)&a1, g_A1);
        float* z2;  cudaGetSymbolAddress((void**)&z2, g_Z2);
        float* w2f; cudaGetSymbolAddress((void**)&w2f, g_W2f);
        sgemm_rowscale<128, 64, 16, 8, 4><<<grid, 256>>>(a1, w2f, rso, z2,
                                                         N_NODES, ENDD, HID1);
    }
    // out = relu(rs_in * agg(Z2) + bh) @ Wo2 + bo2
    k_agg2_head<<<N_NODES / 8, 256>>>(Wo2, bo2, out);
}

// round 3
// speedup vs baseline: 1.7103x; 1.7103x over previous
#include <cuda_runtime.h>
#include <cuda_bf16.h>
#include <cstdint>

#define N_NODES 100000
#define N_EDGES 3200000
#define IN_K    512     // IN_DIM * N_SEQ
#define HID1    256
#define HID2    128
#define ENDD    64

// ---------------- scratch (device globals; no allocation allowed) ----------------
__device__ int   g_deg_out[N_NODES];
__device__ int   g_deg_in[N_NODES];
__device__ int   g_fill[N_NODES];
__device__ float g_rso[N_NODES];
__device__ float g_rsi[N_NODES];
__device__ int   g_rowptr[N_NODES + 1];
__device__ int   g_bsums[512];
__device__ int   g_colidx[N_EDGES];
__device__ float g_Z1[(size_t)N_NODES * HID1];   // 102 MB
__device__ float g_A1[(size_t)N_NODES * HID1];   // 102 MB
__device__ float g_Z2[(size_t)N_NODES * ENDD];   // 25.6 MB
__device__ float g_W2f[HID1 * ENDD];             // W2 @ Wo1 (256x64)
__device__ float g_bh[ENDD];                     // b2 @ Wo1 + bo1

// ---------------- preprocessing kernels ----------------
__global__ void k_zero()
{
    int i = blockIdx.x * blockDim.x + threadIdx.x;
    if (i < N_NODES) { g_deg_out[i] = 0; g_deg_in[i] = 0; g_fill[i] = 0; }
}

__global__ void k_degree(const int* __restrict__ src, const int* __restrict__ dst)
{
    int e = blockIdx.x * blockDim.x + threadIdx.x;
    if (e < N_EDGES) {
        atomicAdd(&g_deg_out[src[e]], 1);
        atomicAdd(&g_deg_in[dst[e]], 1);
    }
}

__global__ void k_rsqrt()
{
    int i = blockIdx.x * blockDim.x + threadIdx.x;
    if (i < N_NODES) {
        g_rso[i] = rsqrtf((float)max(g_deg_out[i], 1));
        g_rsi[i] = rsqrtf((float)max(g_deg_in[i], 1));
    }
}

// exclusive scan of g_deg_in -> g_rowptr  (3 kernels)
__global__ void k_scan1()
{
    __shared__ int s[256];
    int t = threadIdx.x;
    int i = blockIdx.x * 256 + t;
    int v = (i < N_NODES) ? g_deg_in[i] : 0;
    s[t] = v; __syncthreads();
    #pragma unroll
    for (int off = 1; off < 256; off <<= 1) {
        int u = (t >= off) ? s[t - off] : 0;
        __syncthreads();
        s[t] += u;
        __syncthreads();
    }
    if (i < N_NODES) g_rowptr[i] = s[t] - v;   // exclusive within block
    if (t == 255) g_bsums[blockIdx.x] = s[255];
}

__global__ void k_scan2()
{
    __shared__ int s[512];
    const int nb = (N_NODES + 255) / 256;   // 391
    int t = threadIdx.x;
    int v = (t < nb) ? g_bsums[t] : 0;
    s[t] = v; __syncthreads();
    #pragma unroll
    for (int off = 1; off < 512; off <<= 1) {
        int u = (t >= off) ? s[t - off] : 0;
        __syncthreads();
        s[t] += u;
        __syncthreads();
    }
    if (t < nb) g_bsums[t] = s[t] - v;      // exclusive block offsets
}

__global__ void k_scan3()
{
    int i = blockIdx.x * blockDim.x + threadIdx.x;
    if (i < N_NODES) g_rowptr[i] += g_bsums[i >> 8];
    if (i == 0) g_rowptr[N_NODES] = N_EDGES;
}

__global__ void k_fill(const int* __restrict__ src, const int* __restrict__ dst)
{
    int e = blockIdx.x * blockDim.x + threadIdx.x;
    if (e < N_EDGES) {
        int d = dst[e];
        int p = g_rowptr[d] + atomicAdd(&g_fill[d], 1);
        g_colidx[p] = src[e];
    }
}

// W2f = W2 @ Wo1 (256x128 @ 128x64); bh = b2 @ Wo1 + bo1
__global__ void k_fuse(const float* __restrict__ W2, const float* __restrict__ Wo1,
                       const float* __restrict__ b2, const float* __restrict__ bo1)
{
    int j = threadIdx.x;   // 0..63
    int k = blockIdx.x;    // 0..256 (257 blocks; last one = bias)
    if (k < HID1) {
        float s = 0.f;
        #pragma unroll 8
        for (int m = 0; m < HID2; m++) s += W2[k * HID2 + m] * Wo1[m * ENDD + j];
        g_W2f[k * ENDD + j] = s;
    } else {
        float s = bo1[j];
        #pragma unroll 8
        for (int m = 0; m < HID2; m++) s += b2[m] * Wo1[m * ENDD + j];
        g_bh[j] = s;
    }
}

// ---------------- tf32 tensor-core GEMM for layer 1 ----------------
// C[row, col] = rowscale[row] * sum_k A[row,k] * B[k,col]
// M=100000, N=256, K=512. Block 128x128, BK=32, 8 warps (2x4), warp tile 64x32.
// cp.async 2-stage double buffer; cvt.rna at fragment load; padded smem strides.

__device__ __forceinline__ uint32_t f2tf32(float f)
{
    uint32_t r;
    asm volatile("cvt.rna.tf32.f32 %0, %1;" : "=r"(r) : "f"(f));
    return r;
}

__device__ __forceinline__ void mma_tf32(float* c, uint32_t a0, uint32_t a1,
                                         uint32_t a2, uint32_t a3,
                                         uint32_t b0, uint32_t b1)
{
    asm volatile(
        "mma.sync.aligned.m16n8k8.row.col.f32.tf32.tf32.f32 "
        "{%0,%1,%2,%3}, {%4,%5,%6,%7}, {%8,%9}, {%0,%1,%2,%3};\n"
        : "+f"(c[0]), "+f"(c[1]), "+f"(c[2]), "+f"(c[3])
        : "r"(a0), "r"(a1), "r"(a2), "r"(a3), "r"(b0), "r"(b1));
}

#define APITCH 36    // bank = (4*row + k) % 32 -> conflict-free frag loads
#define BPITCH 136   // bank = (8*k + col) % 32 -> conflict-free frag loads
#define ASTAGE (128 * APITCH)
#define BSTAGE (32 * BPITCH)

__global__ void gemm1_tf32(const float* __restrict__ A, const float* __restrict__ B,
                           const float* __restrict__ rowscale, float* __restrict__ C)
{
    constexpr int M = N_NODES, N = HID1, K = IN_K;
    constexpr int NT = K / 32;   // 16 k-tiles

    extern __shared__ float sm[];
    float* As = sm;                  // [2][128][APITCH]
    float* Bs = sm + 2 * ASTAGE;     // [2][32][BPITCH]

    const int tid = threadIdx.x;
    const int lane = tid & 31;
    const int wid = tid >> 5;
    const int warp_m = wid >> 2;           // 0..1
    const int warp_n = wid & 3;            // 0..3
    const int g  = lane >> 2;              // group id 0..7
    const int tc = lane & 3;               // thread-in-group 0..3
    const int blockRow = blockIdx.y * 128;
    const int blockCol = blockIdx.x * 128;

    float acc[4][4][4];
    #pragma unroll
    for (int i = 0; i < 4; i++)
        #pragma unroll
        for (int j = 0; j < 4; j++)
            #pragma unroll
            for (int q = 0; q < 4; q++) acc[i][j][q] = 0.f;

    // per-thread load assignments (4 x 16B for A, 4 x 16B for B per stage)
    int a_r[4], a_c[4], b_r[4], b_c[4];
    #pragma unroll
    for (int i = 0; i < 4; i++) {
        int id = tid + i * 256;
        a_r[i] = id >> 3;         // 0..127
        a_c[i] = (id & 7) * 4;    // 0,4,..,28
        b_r[i] = id >> 5;         // 0..31
        b_c[i] = (id & 31) * 4;   // 0,4,..,124
    }

    auto issue_copy = [&](int stage, int k0) {
        float* asb = As + stage * ASTAGE;
        float* bsb = Bs + stage * BSTAGE;
        #pragma unroll
        for (int i = 0; i < 4; i++) {
            uint32_t dst = (uint32_t)__cvta_generic_to_shared(asb + a_r[i] * APITCH + a_c[i]);
            const float* srcp = A + (size_t)(blockRow + a_r[i]) * K + k0 + a_c[i];
            int sz = (blockRow + a_r[i] < M) ? 16 : 0;
            asm volatile("cp.async.cg.shared.global [%0], [%1], 16, %2;\n"
                         :: "r"(dst), "l"(srcp), "r"(sz));
        }
        #pragma unroll
        for (int i = 0; i < 4; i++) {
            uint32_t dst = (uint32_t)__cvta_generic_to_shared(bsb + b_r[i] * BPITCH + b_c[i]);
            const float* srcp = B + (size_t)(k0 + b_r[i]) * N + blockCol + b_c[i];
            asm volatile("cp.async.cg.shared.global [%0], [%1], 16;\n"
                         :: "r"(dst), "l"(srcp));
        }
        asm volatile("cp.async.commit_group;\n");
    };

    issue_copy(0, 0);

    for (int kt = 0; kt < NT; kt++) {
        if (kt + 1 < NT) {
            issue_copy((kt + 1) & 1, (kt + 1) * 32);
            asm volatile("cp.async.wait_group 1;\n");
        } else {
            asm volatile("cp.async.wait_group 0;\n");
        }
        __syncthreads();

        const float* asb = As + (kt & 1) * ASTAGE;
        const float* bsb = Bs + (kt & 1) * BSTAGE;

        #pragma unroll
        for (int ks = 0; ks < 4; ks++) {
            int k0 = ks * 8;
            uint32_t af[4][4];
            #pragma unroll
            for (int mt = 0; mt < 4; mt++) {
                int row = warp_m * 64 + mt * 16 + g;
                af[mt][0] = f2tf32(asb[(row    ) * APITCH + k0 + tc    ]);
                af[mt][1] = f2tf32(asb[(row + 8) * APITCH + k0 + tc    ]);
                af[mt][2] = f2tf32(asb[(row    ) * APITCH + k0 + tc + 4]);
                af[mt][3] = f2tf32(asb[(row + 8) * APITCH + k0 + tc + 4]);
            }
            uint32_t bf[4][2];
            #pragma unroll
            for (int nt = 0; nt < 4; nt++) {
                int col = warp_n * 32 + nt * 8 + g;
                bf[nt][0] = f2tf32(bsb[(k0 + tc    ) * BPITCH + col]);
                bf[nt][1] = f2tf32(bsb[(k0 + tc + 4) * BPITCH + col]);
            }
            #pragma unroll
            for (int mt = 0; mt < 4; mt++)
                #pragma unroll
                for (int nt = 0; nt < 4; nt++)
                    mma_tf32(acc[mt][nt], af[mt][0], af[mt][1], af[mt][2], af[mt][3],
                             bf[nt][0], bf[nt][1]);
        }
        __syncthreads();
    }

    // epilogue: rowscale + store (float2 per c-pair)
    #pragma unroll
    for (int mt = 0; mt < 4; mt++) {
        int row0 = blockRow + warp_m * 64 + mt * 16 + g;
        int row1 = row0 + 8;
        float s0 = (row0 < M) ? rowscale[row0] : 0.f;
        float s1 = (row1 < M) ? rowscale[row1] : 0.f;
        #pragma unroll
        for (int nt = 0; nt < 4; nt++) {
            int col = blockCol + warp_n * 32 + nt * 8 + tc * 2;
            if (row0 < M) {
                float2 v = make_float2(acc[mt][nt][0] * s0, acc[mt][nt][1] * s0);
                *(float2*)(C + (size_t)row0 * N + col) = v;
            }
            if (row1 < M) {
                float2 v = make_float2(acc[mt][nt][2] * s1, acc[mt][nt][3] * s1);
                *(float2*)(C + (size_t)row1 * N + col) = v;
            }
        }
    }
}

// ---------------- register-blocked SGEMM with per-row output scale (layer 2) ----------------
template<int BM, int BN, int BK, int TM, int TN>
__global__ void sgemm_rowscale(const float* __restrict__ A, const float* __restrict__ B,
                               const float* __restrict__ rowscale, float* __restrict__ C,
                               int M, int N, int K)
{
    constexpr int THREADS = (BM / TM) * (BN / TN);
    __shared__ float As[BK][BM];
    __shared__ float Bs[BK][BN];

    const int tid = threadIdx.x;
    const int tx  = tid % (BN / TN);
    const int ty  = tid / (BN / TN);
    const int blockRow = blockIdx.y * BM;
    const int blockCol = blockIdx.x * BN;

    constexpr int A_PER = (BM * BK / 4) / THREADS;
    constexpr int B_PER = (BK * BN / 4) / THREADS;

    float acc[TM][TN];
    #pragma unroll
    for (int i = 0; i < TM; i++)
        #pragma unroll
        for (int j = 0; j < TN; j++) acc[i][j] = 0.f;

    for (int k0 = 0; k0 < K; k0 += BK) {
        #pragma unroll
        for (int i = 0; i < A_PER; i++) {
            int id = tid + i * THREADS;
            int r  = id / (BK / 4);
            int c4 = id % (BK / 4);
            int grow = blockRow + r;
            float4 v = make_float4(0.f, 0.f, 0.f, 0.f);
            if (grow < M) v = *(const float4*)(A + (size_t)grow * K + k0 + c4 * 4);
            As[c4 * 4 + 0][r] = v.x;
            As[c4 * 4 + 1][r] = v.y;
            As[c4 * 4 + 2][r] = v.z;
            As[c4 * 4 + 3][r] = v.w;
        }
        #pragma unroll
        for (int i = 0; i < B_PER; i++) {
            int id = tid + i * THREADS;
            int r  = id / (BN / 4);
            int c4 = id % (BN / 4);
            *(float4*)&Bs[r][c4 * 4] =
                *(const float4*)(B + (size_t)(k0 + r) * N + blockCol + c4 * 4);
        }
        __syncthreads();

        #pragma unroll
        for (int k = 0; k < BK; k++) {
            float ra[TM], rb[TN];
            #pragma unroll
            for (int i = 0; i < TM; i += 4) {
                float4 t = *(const float4*)&As[k][ty * TM + i];
                ra[i] = t.x; ra[i + 1] = t.y; ra[i + 2] = t.z; ra[i + 3] = t.w;
            }
            #pragma unroll
            for (int j = 0; j < TN; j += 4) {
                float4 t = *(const float4*)&Bs[k][tx * TN + j];
                rb[j] = t.x; rb[j + 1] = t.y; rb[j + 2] = t.z; rb[j + 3] = t.w;
            }
            #pragma unroll
            for (int i = 0; i < TM; i++)
                #pragma unroll
                for (int j = 0; j < TN; j++)
                    acc[i][j] += ra[i] * rb[j];
        }
        __syncthreads();
    }

    #pragma unroll
    for (int i = 0; i < TM; i++) {
        int grow = blockRow + ty * TM + i;
        if (grow >= M) continue;
        float s = rowscale[grow];
        #pragma unroll
        for (int j = 0; j < TN; j += 4) {
            float4 v;
            v.x = acc[i][j + 0] * s;
            v.y = acc[i][j + 1] * s;
            v.z = acc[i][j + 2] * s;
            v.w = acc[i][j + 3] * s;
            *(float4*)(C + (size_t)grow * N + blockCol + tx * TN + j) = v;
        }
    }
}

// ---------------- aggregation layer 1 (dim 256) + relu ----------------
__global__ void k_agg1_relu(const float* __restrict__ b1)
{
    int grp  = threadIdx.x >> 6;
    int lane = threadIdx.x & 63;
    int n = blockIdx.x * 4 + grp;
    if (n >= N_NODES) return;
    int beg = g_rowptr[n], end = g_rowptr[n + 1];

    float4 acc = make_float4(0.f, 0.f, 0.f, 0.f);
    int e = beg;
    for (; e + 4 <= end; e += 4) {
        int c0 = g_colidx[e], c1 = g_colidx[e + 1], c2 = g_colidx[e + 2], c3 = g_colidx[e + 3];
        float4 v0 = *(const float4*)(g_Z1 + (size_t)c0 * HID1 + lane * 4);
        float4 v1 = *(const float4*)(g_Z1 + (size_t)c1 * HID1 + lane * 4);
        float4 v2 = *(const float4*)(g_Z1 + (size_t)c2 * HID1 + lane * 4);
        float4 v3 = *(const float4*)(g_Z1 + (size_t)c3 * HID1 + lane * 4);
        acc.x += (v0.x + v1.x) + (v2.x + v3.x);
        acc.y += (v0.y + v1.y) + (v2.y + v3.y);
        acc.z += (v0.z + v1.z) + (v2.z + v3.z);
        acc.w += (v0.w + v1.w) + (v2.w + v3.w);
    }
    for (; e < end; e++) {
        int c = g_colidx[e];
        float4 v = *(const float4*)(g_Z1 + (size_t)c * HID1 + lane * 4);
        acc.x += v.x; acc.y += v.y; acc.z += v.z; acc.w += v.w;
    }
    float s = g_rsi[n];
    float4 bb = *(const float4*)(b1 + lane * 4);
    float4 o;
    o.x = fmaxf(fmaf(s, acc.x, bb.x), 0.f);
    o.y = fmaxf(fmaf(s, acc.y, bb.y), 0.f);
    o.z = fmaxf(fmaf(s, acc.z, bb.z), 0.f);
    o.w = fmaxf(fmaf(s, acc.w, bb.w), 0.f);
    *(float4*)(g_A1 + (size_t)n * HID1 + lane * 4) = o;
}

// ---------------- aggregation layer 2 (dim 64) + fused head ----------------
__global__ void k_agg2_head(const float* __restrict__ Wo2, const float* __restrict__ bo2,
                            float* __restrict__ out)
{
    int w    = threadIdx.x >> 5;
    int lane = threadIdx.x & 31;
    int n = blockIdx.x * 8 + w;
    if (n >= N_NODES) return;
    int beg = g_rowptr[n], end = g_rowptr[n + 1];

    float2 acc = make_float2(0.f, 0.f);
    int e = beg;
    for (; e + 4 <= end; e += 4) {
        int c0 = g_colidx[e], c1 = g_colidx[e + 1], c2 = g_colidx[e + 2], c3 = g_colidx[e + 3];
        float2 v0 = *(const float2*)(g_Z2 + (size_t)c0 * ENDD + lane * 2);
        float2 v1 = *(const float2*)(g_Z2 + (size_t)c1 * ENDD + lane * 2);
        float2 v2 = *(const float2*)(g_Z2 + (size_t)c2 * ENDD + lane * 2);
        float2 v3 = *(const float2*)(g_Z2 + (size_t)c3 * ENDD + lane * 2);
        acc.x += (v0.x + v1.x) + (v2.x + v3.x);
        acc.y += (v0.y + v1.y) + (v2.y + v3.y);
    }
    for (; e < end; e++) {
        int c = g_colidx[e];
        float2 v = *(const float2*)(g_Z2 + (size_t)c * ENDD + lane * 2);
        acc.x += v.x; acc.y += v.y;
    }
    float s  = g_rsi[n];
    float t0 = fmaxf(fmaf(s, acc.x, g_bh[lane * 2 + 0]), 0.f);
    float t1 = fmaxf(fmaf(s, acc.y, g_bh[lane * 2 + 1]), 0.f);
    float p  = t0 * Wo2[lane * 2] + t1 * Wo2[lane * 2 + 1];
    #pragma unroll
    for (int off = 16; off; off >>= 1) p += __shfl_down_sync(0xffffffffu, p, off);
    if (lane == 0) out[n] = p + bo2[0];
}

// ---------------- launch ----------------
extern "C" void kernel_launch(void* const* d_in, const int* in_sizes, int n_in,
                              void* d_out, int out_size)
{
    const float* features = (const float*)d_in[0];   // [100000, 512]
    const int*   src      = (const int*)d_in[1];
    const int*   dst      = (const int*)d_in[2];
    const float* W1       = (const float*)d_in[3];   // [512, 256]
    const float* b1       = (const float*)d_in[4];
    const float* W2       = (const float*)d_in[5];   // [256, 128]
    const float* b2       = (const float*)d_in[6];
    const float* Wo1      = (const float*)d_in[7];   // [128, 64]
    const float* bo1      = (const float*)d_in[8];
    const float* Wo2      = (const float*)d_in[9];   // [64, 1]
    const float* bo2      = (const float*)d_in[10];
    float* out = (float*)d_out;

    const int nodeBlocks = (N_NODES + 255) / 256;    // 391
    const int edgeBlocks = (N_EDGES + 255) / 256;    // 12500
    const int GEMM1_SMEM = (2 * ASTAGE + 2 * BSTAGE) * sizeof(float);  // 71680 B

    cudaFuncSetAttribute(gemm1_tf32, cudaFuncAttributeMaxDynamicSharedMemorySize,
                         GEMM1_SMEM);

    float *rso, *rsi_unused, *z1, *a1, *z2, *w2f;
    cudaGetSymbolAddress((void**)&rso, g_rso);
    cudaGetSymbolAddress((void**)&z1, g_Z1);
    cudaGetSymbolAddress((void**)&a1, g_A1);
    cudaGetSymbolAddress((void**)&z2, g_Z2);
    cudaGetSymbolAddress((void**)&w2f, g_W2f);
    (void)rsi_unused;

    // launches 1..5 (ncu -s 5 -c 1 captures launch #6 = gemm1_tf32)
    k_zero<<<nodeBlocks, 256>>>();
    k_degree<<<edgeBlocks, 256>>>(src, dst);
    k_rsqrt<<<nodeBlocks, 256>>>();
    k_fuse<<<HID1 + 1, ENDD>>>(W2, Wo1, b2, bo1);
    k_scan1<<<nodeBlocks, 256>>>();

    // launch #6: layer 1 GEMM (tf32 tensor cores): Z1 = rso * (X @ W1)
    {
        dim3 grid(HID1 / 128, (N_NODES + 127) / 128);
        gemm1_tf32<<<grid, 256, GEMM1_SMEM>>>(features, W1, rso, z1);
    }

    // finish CSR build
    k_scan2<<<1, 512>>>();
    k_scan3<<<nodeBlocks, 256>>>();
    k_fill<<<edgeBlocks, 256>>>(src, dst);

    // A1 = relu(rsi * agg(Z1) + b1)
    k_agg1_relu<<<N_NODES / 4, 256>>>(b1);

    // layer 2 (folded with head Linear1): Z2 = rso * (A1 @ (W2@Wo1))
    {
        dim3 grid(ENDD / 64, (N_NODES + 127) / 128);
        sgemm_rowscale<128, 64, 16, 8, 4><<<grid, 256>>>(a1, w2f, rso, z2,
                                                         N_NODES, ENDD, HID1);
    }
    // out = relu(rsi * agg(Z2) + bh) @ Wo2 + bo2
    k_agg2_head<<<N_NODES / 8, 256>>>(Wo2, bo2, out);
}

// round 4
// speedup vs baseline: 1.9667x; 1.1499x over previous
#include <cuda_runtime.h>
#include <cuda_fp16.h>
#include <cuda_bf16.h>
#include <cstdint>

#define N_NODES 100000
#define N_EDGES 3200000
#define IN_K    512     // IN_DIM * N_SEQ
#define HID1    256
#define HID2    128
#define ENDD    64

// ---------------- scratch (device globals; no allocation allowed) ----------------
__device__ int    g_deg_out[N_NODES];
__device__ int    g_deg_in[N_NODES];
__device__ int    g_fill[N_NODES];
__device__ float  g_rso[N_NODES];
__device__ float  g_rsi[N_NODES];
__device__ int    g_rowptr[N_NODES + 1];
__device__ int    g_bsums[512];
__device__ int    g_colidx[N_EDGES];
__device__ __half g_Z1h[(size_t)N_NODES * HID1];  // 51 MB  (L2-resident)
__device__ __half g_A1h[(size_t)N_NODES * HID1];  // 51 MB
__device__ __half g_Z2h[(size_t)N_NODES * ENDD];  // 12.8 MB
__device__ float  g_W2f[HID1 * ENDD];             // W2 @ Wo1 (256x64)
__device__ float  g_bh[ENDD];                     // b2 @ Wo1 + bo1

// ---------------- preprocessing kernels ----------------
__global__ void k_zero()
{
    int i = blockIdx.x * blockDim.x + threadIdx.x;
    if (i < N_NODES) { g_deg_out[i] = 0; g_deg_in[i] = 0; g_fill[i] = 0; }
}

__global__ void k_degree(const int* __restrict__ src, const int* __restrict__ dst)
{
    int e = blockIdx.x * blockDim.x + threadIdx.x;
    if (e < N_EDGES) {
        atomicAdd(&g_deg_out[src[e]], 1);
        atomicAdd(&g_deg_in[dst[e]], 1);
    }
}

__global__ void k_rsqrt()
{
    int i = blockIdx.x * blockDim.x + threadIdx.x;
    if (i < N_NODES) {
        g_rso[i] = rsqrtf((float)max(g_deg_out[i], 1));
        g_rsi[i] = rsqrtf((float)max(g_deg_in[i], 1));
    }
}

// exclusive scan of g_deg_in -> g_rowptr  (3 kernels)
__global__ void k_scan1()
{
    __shared__ int s[256];
    int t = threadIdx.x;
    int i = blockIdx.x * 256 + t;
    int v = (i < N_NODES) ? g_deg_in[i] : 0;
    s[t] = v; __syncthreads();
    #pragma unroll
    for (int off = 1; off < 256; off <<= 1) {
        int u = (t >= off) ? s[t - off] : 0;
        __syncthreads();
        s[t] += u;
        __syncthreads();
    }
    if (i < N_NODES) g_rowptr[i] = s[t] - v;   // exclusive within block
    if (t == 255) g_bsums[blockIdx.x] = s[255];
}

__global__ void k_scan2()
{
    __shared__ int s[512];
    const int nb = (N_NODES + 255) / 256;   // 391
    int t = threadIdx.x;
    int v = (t < nb) ? g_bsums[t] : 0;
    s[t] = v; __syncthreads();
    #pragma unroll
    for (int off = 1; off < 512; off <<= 1) {
        int u = (t >= off) ? s[t - off] : 0;
        __syncthreads();
        s[t] += u;
        __syncthreads();
    }
    if (t < nb) g_bsums[t] = s[t] - v;      // exclusive block offsets
}

__global__ void k_scan3()
{
    int i = blockIdx.x * blockDim.x + threadIdx.x;
    if (i < N_NODES) g_rowptr[i] += g_bsums[i >> 8];
    if (i == 0) g_rowptr[N_NODES] = N_EDGES;
}

__global__ void k_fill(const int* __restrict__ src, const int* __restrict__ dst)
{
    int e = blockIdx.x * blockDim.x + threadIdx.x;
    if (e < N_EDGES) {
        int d = dst[e];
        int p = g_rowptr[d] + atomicAdd(&g_fill[d], 1);
        g_colidx[p] = src[e];
    }
}

// W2f = W2 @ Wo1 (256x128 @ 128x64); bh = b2 @ Wo1 + bo1
__global__ void k_fuse(const float* __restrict__ W2, const float* __restrict__ Wo1,
                       const float* __restrict__ b2, const float* __restrict__ bo1)
{
    int j = threadIdx.x;   // 0..63
    int k = blockIdx.x;    // 0..256 (257 blocks; last one = bias)
    if (k < HID1) {
        float s = 0.f;
        #pragma unroll 8
        for (int m = 0; m < HID2; m++) s += W2[k * HID2 + m] * Wo1[m * ENDD + j];
        g_W2f[k * ENDD + j] = s;
    } else {
        float s = bo1[j];
        #pragma unroll 8
        for (int m = 0; m < HID2; m++) s += b2[m] * Wo1[m * ENDD + j];
        g_bh[j] = s;
    }
}

// ---------------- tf32 tensor-core GEMM for layer 1 (fp16 output) ----------------
__device__ __forceinline__ uint32_t f2tf32(float f)
{
    uint32_t r;
    asm volatile("cvt.rna.tf32.f32 %0, %1;" : "=r"(r) : "f"(f));
    return r;
}

__device__ __forceinline__ void mma_tf32(float* c, uint32_t a0, uint32_t a1,
                                         uint32_t a2, uint32_t a3,
                                         uint32_t b0, uint32_t b1)
{
    asm volatile(
        "mma.sync.aligned.m16n8k8.row.col.f32.tf32.tf32.f32 "
        "{%0,%1,%2,%3}, {%4,%5,%6,%7}, {%8,%9}, {%0,%1,%2,%3};\n"
        : "+f"(c[0]), "+f"(c[1]), "+f"(c[2]), "+f"(c[3])
        : "r"(a0), "r"(a1), "r"(a2), "r"(a3), "r"(b0), "r"(b1));
}

#define APITCH 36    // bank = (4*row + k) % 32 -> conflict-free frag loads
#define BPITCH 136   // bank = (8*k + col) % 32 -> conflict-free frag loads
#define ASTAGE (128 * APITCH)
#define BSTAGE (32 * BPITCH)

__global__ void gemm1_tf32(const float* __restrict__ A, const float* __restrict__ B,
                           const float* __restrict__ rowscale, __half* __restrict__ C)
{
    constexpr int M = N_NODES, N = HID1, K = IN_K;
    constexpr int NT = K / 32;   // 16 k-tiles

    extern __shared__ float sm[];
    float* As = sm;                  // [2][128][APITCH]
    float* Bs = sm + 2 * ASTAGE;     // [2][32][BPITCH]

    const int tid = threadIdx.x;
    const int lane = tid & 31;
    const int wid = tid >> 5;
    const int warp_m = wid >> 2;           // 0..1
    const int warp_n = wid & 3;            // 0..3
    const int g  = lane >> 2;              // group id 0..7
    const int tc = lane & 3;               // thread-in-group 0..3
    const int blockRow = blockIdx.y * 128;
    const int blockCol = blockIdx.x * 128;

    float acc[4][4][4];
    #pragma unroll
    for (int i = 0; i < 4; i++)
        #pragma unroll
        for (int j = 0; j < 4; j++)
            #pragma unroll
            for (int q = 0; q < 4; q++) acc[i][j][q] = 0.f;

    int a_r[4], a_c[4], b_r[4], b_c[4];
    #pragma unroll
    for (int i = 0; i < 4; i++) {
        int id = tid + i * 256;
        a_r[i] = id >> 3;         // 0..127
        a_c[i] = (id & 7) * 4;    // 0,4,..,28
        b_r[i] = id >> 5;         // 0..31
        b_c[i] = (id & 31) * 4;   // 0,4,..,124
    }

    auto issue_copy = [&](int stage, int k0) {
        float* asb = As + stage * ASTAGE;
        float* bsb = Bs + stage * BSTAGE;
        #pragma unroll
        for (int i = 0; i < 4; i++) {
            uint32_t dst = (uint32_t)__cvta_generic_to_shared(asb + a_r[i] * APITCH + a_c[i]);
            const float* srcp = A + (size_t)(blockRow + a_r[i]) * K + k0 + a_c[i];
            int sz = (blockRow + a_r[i] < M) ? 16 : 0;
            asm volatile("cp.async.cg.shared.global [%0], [%1], 16, %2;\n"
                         :: "r"(dst), "l"(srcp), "r"(sz));
        }
        #pragma unroll
        for (int i = 0; i < 4; i++) {
            uint32_t dst = (uint32_t)__cvta_generic_to_shared(bsb + b_r[i] * BPITCH + b_c[i]);
            const float* srcp = B + (size_t)(k0 + b_r[i]) * N + blockCol + b_c[i];
            asm volatile("cp.async.cg.shared.global [%0], [%1], 16;\n"
                         :: "r"(dst), "l"(srcp));
        }
        asm volatile("cp.async.commit_group;\n");
    };

    issue_copy(0, 0);

    for (int kt = 0; kt < NT; kt++) {
        if (kt + 1 < NT) {
            issue_copy((kt + 1) & 1, (kt + 1) * 32);
            asm volatile("cp.async.wait_group 1;\n");
        } else {
            asm volatile("cp.async.wait_group 0;\n");
        }
        __syncthreads();

        const float* asb = As + (kt & 1) * ASTAGE;
        const float* bsb = Bs + (kt & 1) * BSTAGE;

        #pragma unroll
        for (int ks = 0; ks < 4; ks++) {
            int k0 = ks * 8;
            uint32_t af[4][4];
            #pragma unroll
            for (int mt = 0; mt < 4; mt++) {
                int row = warp_m * 64 + mt * 16 + g;
                af[mt][0] = f2tf32(asb[(row    ) * APITCH + k0 + tc    ]);
                af[mt][1] = f2tf32(asb[(row + 8) * APITCH + k0 + tc    ]);
                af[mt][2] = f2tf32(asb[(row    ) * APITCH + k0 + tc + 4]);
                af[mt][3] = f2tf32(asb[(row + 8) * APITCH + k0 + tc + 4]);
            }
            uint32_t bf[4][2];
            #pragma unroll
            for (int nt = 0; nt < 4; nt++) {
                int col = warp_n * 32 + nt * 8 + g;
                bf[nt][0] = f2tf32(bsb[(k0 + tc    ) * BPITCH + col]);
                bf[nt][1] = f2tf32(bsb[(k0 + tc + 4) * BPITCH + col]);
            }
            #pragma unroll
            for (int mt = 0; mt < 4; mt++)
                #pragma unroll
                for (int nt = 0; nt < 4; nt++)
                    mma_tf32(acc[mt][nt], af[mt][0], af[mt][1], af[mt][2], af[mt][3],
                             bf[nt][0], bf[nt][1]);
        }
        __syncthreads();
    }

    // epilogue: rowscale + half2 store
    #pragma unroll
    for (int mt = 0; mt < 4; mt++) {
        int row0 = blockRow + warp_m * 64 + mt * 16 + g;
        int row1 = row0 + 8;
        float s0 = (row0 < M) ? rowscale[row0] : 0.f;
        float s1 = (row1 < M) ? rowscale[row1] : 0.f;
        #pragma unroll
        for (int nt = 0; nt < 4; nt++) {
            int col = blockCol + warp_n * 32 + nt * 8 + tc * 2;
            if (row0 < M)
                *(__half2*)(C + (size_t)row0 * N + col) =
                    __floats2half2_rn(acc[mt][nt][0] * s0, acc[mt][nt][1] * s0);
            if (row1 < M)
                *(__half2*)(C + (size_t)row1 * N + col) =
                    __floats2half2_rn(acc[mt][nt][2] * s1, acc[mt][nt][3] * s1);
        }
    }
}

// ---------------- aggregation layer 1 (dim 256, fp16 in/out) + relu ----------------
// block = 256 threads = 4 groups of 64 lanes; group = one dst node; lane owns 4 halves
__global__ void k_agg1_relu(const float* __restrict__ b1)
{
    int grp  = threadIdx.x >> 6;
    int lane = threadIdx.x & 63;
    int n = blockIdx.x * 4 + grp;
    if (n >= N_NODES) return;
    int beg = g_rowptr[n], end = g_rowptr[n + 1];

    float4 acc = make_float4(0.f, 0.f, 0.f, 0.f);
    int e = beg;
    #define LOAD4H(c) (*(const uint2*)(g_Z1h + (size_t)(c) * HID1 + (lane << 2)))
    #define ACC4H(u) do { \
        __half2 h0 = *reinterpret_cast<__half2*>(&(u).x); \
        __half2 h1 = *reinterpret_cast<__half2*>(&(u).y); \
        float2 f0 = __half22float2(h0); \
        float2 f1 = __half22float2(h1); \
        acc.x += f0.x; acc.y += f0.y; acc.z += f1.x; acc.w += f1.y; } while (0)
    for (; e + 4 <= end; e += 4) {
        int c0 = g_colidx[e], c1 = g_colidx[e + 1], c2 = g_colidx[e + 2], c3 = g_colidx[e + 3];
        uint2 u0 = LOAD4H(c0);
        uint2 u1 = LOAD4H(c1);
        uint2 u2 = LOAD4H(c2);
        uint2 u3 = LOAD4H(c3);
        ACC4H(u0); ACC4H(u1); ACC4H(u2); ACC4H(u3);
    }
    for (; e < end; e++) {
        int c = g_colidx[e];
        uint2 u = LOAD4H(c);
        ACC4H(u);
    }
    #undef LOAD4H
    #undef ACC4H
    float s = g_rsi[n];
    float4 bb = *(const float4*)(b1 + lane * 4);
    __half2 o0 = __floats2half2_rn(fmaxf(fmaf(s, acc.x, bb.x), 0.f),
                                   fmaxf(fmaf(s, acc.y, bb.y), 0.f));
    __half2 o1 = __floats2half2_rn(fmaxf(fmaf(s, acc.z, bb.z), 0.f),
                                   fmaxf(fmaf(s, acc.w, bb.w), 0.f));
    uint2 st;
    st.x = *reinterpret_cast<uint32_t*>(&o0);
    st.y = *reinterpret_cast<uint32_t*>(&o1);
    *(uint2*)(g_A1h + (size_t)n * HID1 + (lane << 2)) = st;
}

// ---------------- GEMM2: Z2 = rso * (A1h @ W2f), A half, B/accum fp32, C half ----
// BM=128 BN=64 BK=16 TM=8 TN=4, 256 threads
__global__ void gemm2_h(const __half* __restrict__ A, const float* __restrict__ B,
                        const float* __restrict__ rowscale, __half* __restrict__ C)
{
    constexpr int M = N_NODES, N = ENDD, K = HID1;
    constexpr int BM = 128, BN = 64, BK = 16, TM = 8, TN = 4;
    __shared__ float As[BK][BM];
    __shared__ float Bs[BK][BN];

    const int tid = threadIdx.x;
    const int tx  = tid % (BN / TN);   // 16
    const int ty  = tid / (BN / TN);   // 16
    const int blockRow = blockIdx.y * BM;
    const int blockCol = blockIdx.x * BN;

    float acc[TM][TN];
    #pragma unroll
    for (int i = 0; i < TM; i++)
        #pragma unroll
        for (int j = 0; j < TN; j++) acc[i][j] = 0.f;

    for (int k0 = 0; k0 < K; k0 += BK) {
        // A tile: 128x16 halves; 512 quad-slots / 256 threads = 2 per thread
        #pragma unroll
        for (int i = 0; i < 2; i++) {
            int id = tid + i * 256;
            int r  = id >> 2;            // 0..127
            int c4 = (id & 3) * 4;       // 0,4,8,12
            int grow = blockRow + r;
            uint2 u = make_uint2(0, 0);
            if (grow < M) u = *(const uint2*)(A + (size_t)grow * K + k0 + c4);
            __half2 h0 = *reinterpret_cast<__half2*>(&u.x);
            __half2 h1 = *reinterpret_cast<__half2*>(&u.y);
            float2 f0 = __half22float2(h0);
            float2 f1 = __half22float2(h1);
            As[c4 + 0][r] = f0.x;
            As[c4 + 1][r] = f0.y;
            As[c4 + 2][r] = f1.x;
            As[c4 + 3][r] = f1.y;
        }
        // B tile: 16x64 fp32; 256 float4-slots / 256 threads = 1 per thread
        {
            int r  = tid >> 4;           // 0..15
            int c4 = (tid & 15) * 4;     // 0..60
            *(float4*)&Bs[r][c4] =
                *(const float4*)(B + (size_t)(k0 + r) * N + blockCol + c4);
        }
        __syncthreads();

        #pragma unroll
        for (int k = 0; k < BK; k++) {
            float ra[TM], rb[TN];
            #pragma unroll
            for (int i = 0; i < TM; i += 4) {
                float4 t = *(const float4*)&As[k][ty * TM + i];
                ra[i] = t.x; ra[i + 1] = t.y; ra[i + 2] = t.z; ra[i + 3] = t.w;
            }
            {
                float4 t = *(const float4*)&Bs[k][tx * TN];
                rb[0] = t.x; rb[1] = t.y; rb[2] = t.z; rb[3] = t.w;
            }
            #pragma unroll
            for (int i = 0; i < TM; i++)
                #pragma unroll
                for (int j = 0; j < TN; j++)
                    acc[i][j] += ra[i] * rb[j];
        }
        __syncthreads();
    }

    #pragma unroll
    for (int i = 0; i < TM; i++) {
        int grow = blockRow + ty * TM + i;
        if (grow >= M) continue;
        float s = rowscale[grow];
        __half2 p0 = __floats2half2_rn(acc[i][0] * s, acc[i][1] * s);
        __half2 p1 = __floats2half2_rn(acc[i][2] * s, acc[i][3] * s);
        uint2 st;
        st.x = *reinterpret_cast<uint32_t*>(&p0);
        st.y = *reinterpret_cast<uint32_t*>(&p1);
        *(uint2*)(C + (size_t)grow * N + blockCol + tx * TN) = st;
    }
}

// ---------------- aggregation layer 2 (dim 64, fp16) + fused head ----------------
// block = 256 threads = 8 warps; warp = one dst node; lane owns a half2
__global__ void k_agg2_head(const float* __restrict__ Wo2, const float* __restrict__ bo2,
                            float* __restrict__ out)
{
    int w    = threadIdx.x >> 5;
    int lane = threadIdx.x & 31;
    int n = blockIdx.x * 8 + w;
    if (n >= N_NODES) return;
    int beg = g_rowptr[n], end = g_rowptr[n + 1];

    float2 acc = make_float2(0.f, 0.f);
    int e = beg;
    for (; e + 4 <= end; e += 4) {
        int c0 = g_colidx[e], c1 = g_colidx[e + 1], c2 = g_colidx[e + 2], c3 = g_colidx[e + 3];
        float2 f0 = __half22float2(*(const __half2*)(g_Z2h + (size_t)c0 * ENDD + (lane << 1)));
        float2 f1 = __half22float2(*(const __half2*)(g_Z2h + (size_t)c1 * ENDD + (lane << 1)));
        float2 f2 = __half22float2(*(const __half2*)(g_Z2h + (size_t)c2 * ENDD + (lane << 1)));
        float2 f3 = __half22float2(*(const __half2*)(g_Z2h + (size_t)c3 * ENDD + (lane << 1)));
        acc.x += (f0.x + f1.x) + (f2.x + f3.x);
        acc.y += (f0.y + f1.y) + (f2.y + f3.y);
    }
    for (; e < end; e++) {
        int c = g_colidx[e];
        float2 f = __half22float2(*(const __half2*)(g_Z2h + (size_t)c * ENDD + (lane << 1)));
        acc.x += f.x; acc.y += f.y;
    }
    float s  = g_rsi[n];
    float t0 = fmaxf(fmaf(s, acc.x, g_bh[lane * 2 + 0]), 0.f);
    float t1 = fmaxf(fmaf(s, acc.y, g_bh[lane * 2 + 1]), 0.f);
    float p  = t0 * Wo2[lane * 2] + t1 * Wo2[lane * 2 + 1];
    #pragma unroll
    for (int off = 16; off; off >>= 1) p += __shfl_down_sync(0xffffffffu, p, off);
    if (lane == 0) out[n] = p + bo2[0];
}

// ---------------- launch ----------------
extern "C" void kernel_launch(void* const* d_in, const int* in_sizes, int n_in,
                              void* d_out, int out_size)
{
    const float* features = (const float*)d_in[0];   // [100000, 512]
    const int*   src      = (const int*)d_in[1];
    const int*   dst      = (const int*)d_in[2];
    const float* W1       = (const float*)d_in[3];   // [512, 256]
    const float* b1       = (const float*)d_in[4];
    const float* W2       = (const float*)d_in[5];   // [256, 128]
    const float* b2       = (const float*)d_in[6];
    const float* Wo1      = (const float*)d_in[7];   // [128, 64]
    const float* bo1      = (const float*)d_in[8];
    const float* Wo2      = (const float*)d_in[9];   // [64, 1]
    const float* bo2      = (const float*)d_in[10];
    float* out = (float*)d_out;

    const int nodeBlocks = (N_NODES + 255) / 256;    // 391
    const int edgeBlocks = (N_EDGES + 255) / 256;    // 12500
    const int GEMM1_SMEM = (2 * ASTAGE + 2 * BSTAGE) * sizeof(float);  // 71680 B

    cudaFuncSetAttribute(gemm1_tf32, cudaFuncAttributeMaxDynamicSharedMemorySize,
                         GEMM1_SMEM);

    float *rso;
    __half *z1, *a1, *z2;
    float *w2f;
    cudaGetSymbolAddress((void**)&rso, g_rso);
    cudaGetSymbolAddress((void**)&z1, g_Z1h);
    cudaGetSymbolAddress((void**)&a1, g_A1h);
    cudaGetSymbolAddress((void**)&z2, g_Z2h);
    cudaGetSymbolAddress((void**)&w2f, g_W2f);

    // launches 1..3
    k_zero<<<nodeBlocks, 256>>>();
    k_degree<<<edgeBlocks, 256>>>(src, dst);
    k_rsqrt<<<nodeBlocks, 256>>>();

    // launch #4 (ncu-captured): layer-1 tf32 GEMM: Z1h = rso * (X @ W1)
    {
        dim3 grid(HID1 / 128, (N_NODES + 127) / 128);
        gemm1_tf32<<<grid, 256, GEMM1_SMEM>>>(features, W1, rso, z1);
    }

    // CSR build + weight folding
    k_scan1<<<nodeBlocks, 256>>>();
    k_scan2<<<1, 512>>>();
    k_scan3<<<nodeBlocks, 256>>>();
    k_fill<<<edgeBlocks, 256>>>(src, dst);
    k_fuse<<<HID1 + 1, ENDD>>>(W2, Wo1, b2, bo1);

    // A1h = relu(rsi * agg(Z1h) + b1)
    k_agg1_relu<<<N_NODES / 4, 256>>>(b1);

    // layer 2 (folded with head Linear1): Z2h = rso * (A1h @ (W2@Wo1))
    {
        dim3 grid(ENDD / 64, (N_NODES + 127) / 128);
        gemm2_h<<<grid, 256>>>(a1, w2f, rso, z2);
    }
    // out = relu(rsi * agg(Z2h) + bh) @ Wo2 + bo2
    k_agg2_head<<<N_NODES / 8, 256>>>(Wo2, bo2, out);
}

// round 5
// speedup vs baseline: 2.5693x; 1.3064x over previous
#include <cuda_runtime.h>
#include <cuda_fp16.h>
#include <cuda_bf16.h>
#include <cstdint>

#define N_NODES 100000
#define N_EDGES 3200000
#define IN_K    512     // IN_DIM * N_SEQ
#define HID1    256
#define HID2    128
#define ENDD    64

// ---------------- scratch (device globals; no allocation allowed) ----------------
__device__ int    g_deg_out[N_NODES];
__device__ int    g_deg_in[N_NODES];
__device__ int    g_fill[N_NODES];
__device__ float  g_rso[N_NODES];
__device__ float  g_rsi[N_NODES];
__device__ int    g_rowptr[N_NODES + 1];
__device__ int    g_bsums[512];
__device__ int    g_colidx[N_EDGES];
__device__ __half g_W1t[HID1 * IN_K];             // W1 transposed fp16 [n=256][k=512]
__device__ __half g_Z1h[(size_t)N_NODES * HID1];  // 51 MB  (L2-resident)
__device__ __half g_A1h[(size_t)N_NODES * HID1];  // 51 MB
__device__ __half g_Z2h[(size_t)N_NODES * ENDD];  // 12.8 MB
__device__ __half g_W2ft[ENDD * HID1];            // (W2@Wo1)^T fp16 [n=64][k=256]
__device__ float  g_bh[ENDD];                     // b2 @ Wo1 + bo1

// ---------------- preprocessing kernels ----------------
// zero degree arrays AND convert W1 (512x256 fp32) -> W1t (256x512 half)
__global__ void k_zero_cvt(const float* __restrict__ W1)
{
    int i = blockIdx.x * blockDim.x + threadIdx.x;
    if (i < N_NODES) { g_deg_out[i] = 0; g_deg_in[i] = 0; g_fill[i] = 0; }
    if (i < HID1 * IN_K) {
        int n = i >> 9;          // 0..255
        int k = i & 511;         // 0..511
        g_W1t[i] = __float2half(W1[k * HID1 + n]);
    }
}

__global__ void k_degree(const int* __restrict__ src, const int* __restrict__ dst)
{
    int e = blockIdx.x * blockDim.x + threadIdx.x;
    if (e < N_EDGES) {
        atomicAdd(&g_deg_out[src[e]], 1);
        atomicAdd(&g_deg_in[dst[e]], 1);
    }
}

__global__ void k_rsqrt()
{
    int i = blockIdx.x * blockDim.x + threadIdx.x;
    if (i < N_NODES) {
        g_rso[i] = rsqrtf((float)max(g_deg_out[i], 1));
        g_rsi[i] = rsqrtf((float)max(g_deg_in[i], 1));
    }
}

// exclusive scan of g_deg_in -> g_rowptr  (3 kernels)
__global__ void k_scan1()
{
    __shared__ int s[256];
    int t = threadIdx.x;
    int i = blockIdx.x * 256 + t;
    int v = (i < N_NODES) ? g_deg_in[i] : 0;
    s[t] = v; __syncthreads();
    #pragma unroll
    for (int off = 1; off < 256; off <<= 1) {
        int u = (t >= off) ? s[t - off] : 0;
        __syncthreads();
        s[t] += u;
        __syncthreads();
    }
    if (i < N_NODES) g_rowptr[i] = s[t] - v;
    if (t == 255) g_bsums[blockIdx.x] = s[255];
}

__global__ void k_scan2()
{
    __shared__ int s[512];
    const int nb = (N_NODES + 255) / 256;   // 391
    int t = threadIdx.x;
    int v = (t < nb) ? g_bsums[t] : 0;
    s[t] = v; __syncthreads();
    #pragma unroll
    for (int off = 1; off < 512; off <<= 1) {
        int u = (t >= off) ? s[t - off] : 0;
        __syncthreads();
        s[t] += u;
        __syncthreads();
    }
    if (t < nb) g_bsums[t] = s[t] - v;
}

__global__ void k_scan3()
{
    int i = blockIdx.x * blockDim.x + threadIdx.x;
    if (i < N_NODES) g_rowptr[i] += g_bsums[i >> 8];
    if (i == 0) g_rowptr[N_NODES] = N_EDGES;
}

__global__ void k_fill(const int* __restrict__ src, const int* __restrict__ dst)
{
    int e = blockIdx.x * blockDim.x + threadIdx.x;
    if (e < N_EDGES) {
        int d = dst[e];
        int p = g_rowptr[d] + atomicAdd(&g_fill[d], 1);
        g_colidx[p] = src[e];
    }
}

// W2ft[j][k] = (W2 @ Wo1)[k][j] as half; bh = b2 @ Wo1 + bo1
__global__ void k_fuse(const float* __restrict__ W2, const float* __restrict__ Wo1,
                       const float* __restrict__ b2, const float* __restrict__ bo1)
{
    int j = threadIdx.x;   // 0..63
    int k = blockIdx.x;    // 0..256 (257 blocks; last = bias)
    if (k < HID1) {
        float s = 0.f;
        #pragma unroll 8
        for (int m = 0; m < HID2; m++) s += W2[k * HID2 + m] * Wo1[m * ENDD + j];
        g_W2ft[j * HID1 + k] = __float2half(s);
    } else {
        float s = bo1[j];
        #pragma unroll 8
        for (int m = 0; m < HID2; m++) s += b2[m] * Wo1[m * ENDD + j];
        g_bh[j] = s;
    }
}

// ---------------- fp16 HMMA helpers ----------------
__device__ __forceinline__ void mma_f16(float* c, uint32_t a0, uint32_t a1,
                                        uint32_t a2, uint32_t a3,
                                        uint32_t b0, uint32_t b1)
{
    asm volatile(
        "mma.sync.aligned.m16n8k16.row.col.f32.f16.f16.f32 "
        "{%0,%1,%2,%3}, {%4,%5,%6,%7}, {%8,%9}, {%0,%1,%2,%3};\n"
        : "+f"(c[0]), "+f"(c[1]), "+f"(c[2]), "+f"(c[3])
        : "r"(a0), "r"(a1), "r"(a2), "r"(a3), "r"(b0), "r"(b1));
}

#define HPITCH 40   // halves; frag LDS word = 20*g + tc -> conflict-free

__device__ __forceinline__ uint32_t lds_h2(const __half* p)
{
    return *reinterpret_cast<const uint32_t*>(p);
}

// ---------------- GEMM1: Z1h = rso * (X @ W1), fp16 HMMA ----------------
// X fp32 [100000,512] (cvt to half at STS), W1t half [256][512].
// BM=128 BN=128 BK=32, 8 warps (2x4), warp tile 64x32.
__global__ void __launch_bounds__(256, 2)
gemm1_h(const float* __restrict__ A, const float* __restrict__ rowscale,
        __half* __restrict__ C)
{
    constexpr int M = N_NODES, N = HID1, K = IN_K;
    constexpr int NT = K / 32;   // 16

    __shared__ __half As[2][128][HPITCH];
    __shared__ __half Bs[2][128][HPITCH];

    const int tid = threadIdx.x;
    const int lane = tid & 31;
    const int wid = tid >> 5;
    const int warp_m = wid >> 2;        // 0..1
    const int warp_n = wid & 3;         // 0..3
    const int g  = lane >> 2;           // 0..7
    const int tc = lane & 3;            // 0..3
    const int blockRow = blockIdx.y * 128;
    const int blockCol = blockIdx.x * 128;

    float acc[4][4][4];
    #pragma unroll
    for (int i = 0; i < 4; i++)
        #pragma unroll
        for (int j = 0; j < 4; j++)
            #pragma unroll
            for (int q = 0; q < 4; q++) acc[i][j][q] = 0.f;

    // A staging: 4 float4 per thread per tile (128 rows x 32 k fp32)
    int a_r[4], a_c[4];
    #pragma unroll
    for (int i = 0; i < 4; i++) {
        int slot = tid + i * 256;       // 0..1023
        a_r[i] = slot >> 3;             // 0..127
        a_c[i] = (slot & 7) * 4;        // 0..28
    }
    // B: 2 cp.async 16B chunks per thread per tile (128 n x 32 k half)
    int b_n[2], b_c[2];
    #pragma unroll
    for (int i = 0; i < 2; i++) {
        int id = tid + i * 256;         // 0..511
        b_n[i] = id >> 2;               // 0..127
        b_c[i] = (id & 3) * 8;          // 0,8,16,24
    }

    float4 Areg[4];

    auto ldg_A = [&](int k0) {
        #pragma unroll
        for (int i = 0; i < 4; i++) {
            int grow = blockRow + a_r[i];
            Areg[i] = (grow < M) ? *(const float4*)(A + (size_t)grow * K + k0 + a_c[i])
                                 : make_float4(0.f, 0.f, 0.f, 0.f);
        }
    };
    auto sts_A = [&](int stage) {
        #pragma unroll
        for (int i = 0; i < 4; i++) {
            __half2 h0 = __floats2half2_rn(Areg[i].x, Areg[i].y);
            __half2 h1 = __floats2half2_rn(Areg[i].z, Areg[i].w);
            uint2 u;
            u.x = *reinterpret_cast<uint32_t*>(&h0);
            u.y = *reinterpret_cast<uint32_t*>(&h1);
            *(uint2*)&As[stage][a_r[i]][a_c[i]] = u;
        }
    };
    auto cp_B = [&](int stage, int k0) {
        #pragma unroll
        for (int i = 0; i < 2; i++) {
            uint32_t dst = (uint32_t)__cvta_generic_to_shared(&Bs[stage][b_n[i]][b_c[i]]);
            const __half* srcp = g_W1t + (size_t)(blockCol + b_n[i]) * K + k0 + b_c[i];
            asm volatile("cp.async.cg.shared.global [%0], [%1], 16;\n"
                         :: "r"(dst), "l"(srcp));
        }
        asm volatile("cp.async.commit_group;\n");
    };

    // prologue
    ldg_A(0);
    cp_B(0, 0);
    sts_A(0);

    for (int kt = 0; kt < NT; kt++) {
        asm volatile("cp.async.wait_group 0;\n");
        __syncthreads();
        if (kt + 1 < NT) {
            ldg_A((kt + 1) * 32);
            cp_B((kt + 1) & 1, (kt + 1) * 32);
        }

        const int st = kt & 1;
        #pragma unroll
        for (int ks = 0; ks < 2; ks++) {
            const int kb = ks * 16;
            uint32_t af[4][4];
            #pragma unroll
            for (int mt = 0; mt < 4; mt++) {
                int row = warp_m * 64 + mt * 16 + g;
                af[mt][0] = lds_h2(&As[st][row    ][kb + 2 * tc    ]);
                af[mt][1] = lds_h2(&As[st][row + 8][kb + 2 * tc    ]);
                af[mt][2] = lds_h2(&As[st][row    ][kb + 2 * tc + 8]);
                af[mt][3] = lds_h2(&As[st][row + 8][kb + 2 * tc + 8]);
            }
            uint32_t bf[4][2];
            #pragma unroll
            for (int nt = 0; nt < 4; nt++) {
                int n = warp_n * 32 + nt * 8 + g;
                bf[nt][0] = lds_h2(&Bs[st][n][kb + 2 * tc    ]);
                bf[nt][1] = lds_h2(&Bs[st][n][kb + 2 * tc + 8]);
            }
            #pragma unroll
            for (int mt = 0; mt < 4; mt++)
                #pragma unroll
                for (int nt = 0; nt < 4; nt++)
                    mma_f16(acc[mt][nt], af[mt][0], af[mt][1], af[mt][2], af[mt][3],
                            bf[nt][0], bf[nt][1]);
        }
        if (kt + 1 < NT) sts_A((kt + 1) & 1);
    }

    // epilogue: rowscale + half2 store
    #pragma unroll
    for (int mt = 0; mt < 4; mt++) {
        int row0 = blockRow + warp_m * 64 + mt * 16 + g;
        int row1 = row0 + 8;
        float s0 = (row0 < M) ? rowscale[row0] : 0.f;
        float s1 = (row1 < M) ? rowscale[row1] : 0.f;
        #pragma unroll
        for (int nt = 0; nt < 4; nt++) {
            int col = blockCol + warp_n * 32 + nt * 8 + tc * 2;
            if (row0 < M)
                *(__half2*)(C + (size_t)row0 * N + col) =
                    __floats2half2_rn(acc[mt][nt][0] * s0, acc[mt][nt][1] * s0);
            if (row1 < M)
                *(__half2*)(C + (size_t)row1 * N + col) =
                    __floats2half2_rn(acc[mt][nt][2] * s1, acc[mt][nt][3] * s1);
        }
    }
}

// ---------------- GEMM2: Z2h = rso * (A1h @ W2f), fp16 HMMA ----------------
// A1h half [100000,256], W2ft half [64][256]. BM=128 BN=64 BK=32, 8 warps (4x2),
// warp tile 32x32.
__global__ void __launch_bounds__(256, 2)
gemm2_h(const __half* __restrict__ A, const float* __restrict__ rowscale,
        __half* __restrict__ C)
{
    constexpr int M = N_NODES, N = ENDD, K = HID1;
    constexpr int NT = K / 32;   // 8

    __shared__ __half As[2][128][HPITCH];
    __shared__ __half Bs[2][64][HPITCH];

    const int tid = threadIdx.x;
    const int lane = tid & 31;
    const int wid = tid >> 5;
    const int warp_m = wid >> 1;        // 0..3
    const int warp_n = wid & 1;         // 0..1
    const int g  = lane >> 2;
    const int tc = lane & 3;
    const int blockRow = blockIdx.y * 128;

    float acc[2][4][4];
    #pragma unroll
    for (int i = 0; i < 2; i++)
        #pragma unroll
        for (int j = 0; j < 4; j++)
            #pragma unroll
            for (int q = 0; q < 4; q++) acc[i][j][q] = 0.f;

    // A: 2 chunks per thread; B: 1 chunk per thread
    int a_r[2], a_c[2];
    #pragma unroll
    for (int i = 0; i < 2; i++) {
        int id = tid + i * 256;
        a_r[i] = id >> 2;
        a_c[i] = (id & 3) * 8;
    }
    const int bn = tid >> 2;            // 0..63
    const int bc = (tid & 3) * 8;

    auto cp_AB = [&](int stage, int k0) {
        #pragma unroll
        for (int i = 0; i < 2; i++) {
            uint32_t dst = (uint32_t)__cvta_generic_to_shared(&As[stage][a_r[i]][a_c[i]]);
            const __half* srcp = A + (size_t)(blockRow + a_r[i]) * K + k0 + a_c[i];
            int sz = (blockRow + a_r[i] < M) ? 16 : 0;
            asm volatile("cp.async.cg.shared.global [%0], [%1], 16, %2;\n"
                         :: "r"(dst), "l"(srcp), "r"(sz));
        }
        {
            uint32_t dst = (uint32_t)__cvta_generic_to_shared(&Bs[stage][bn][bc]);
            const __half* srcp = g_W2ft + (size_t)bn * K + k0 + bc;
            asm volatile("cp.async.cg.shared.global [%0], [%1], 16;\n"
                         :: "r"(dst), "l"(srcp));
        }
        asm volatile("cp.async.commit_group;\n");
    };

    cp_AB(0, 0);

    for (int kt = 0; kt < NT; kt++) {
        asm volatile("cp.async.wait_group 0;\n");
        __syncthreads();
        if (kt + 1 < NT) cp_AB((kt + 1) & 1, (kt + 1) * 32);

        const int st = kt & 1;
        #pragma unroll
        for (int ks = 0; ks < 2; ks++) {
            const int kb = ks * 16;
            uint32_t af[2][4];
            #pragma unroll
            for (int mt = 0; mt < 2; mt++) {
                int row = warp_m * 32 + mt * 16 + g;
                af[mt][0] = lds_h2(&As[st][row    ][kb + 2 * tc    ]);
                af[mt][1] = lds_h2(&As[st][row + 8][kb + 2 * tc    ]);
                af[mt][2] = lds_h2(&As[st][row    ][kb + 2 * tc + 8]);
                af[mt][3] = lds_h2(&As[st][row + 8][kb + 2 * tc + 8]);
            }
            uint32_t bf[4][2];
            #pragma unroll
            for (int nt = 0; nt < 4; nt++) {
                int n = warp_n * 32 + nt * 8 + g;
                bf[nt][0] = lds_h2(&Bs[st][n][kb + 2 * tc    ]);
                bf[nt][1] = lds_h2(&Bs[st][n][kb + 2 * tc + 8]);
            }
            #pragma unroll
            for (int mt = 0; mt < 2; mt++)
                #pragma unroll
                for (int nt = 0; nt < 4; nt++)
                    mma_f16(acc[mt][nt], af[mt][0], af[mt][1], af[mt][2], af[mt][3],
                            bf[nt][0], bf[nt][1]);
        }
    }

    #pragma unroll
    for (int mt = 0; mt < 2; mt++) {
        int row0 = blockRow + warp_m * 32 + mt * 16 + g;
        int row1 = row0 + 8;
        float s0 = (row0 < M) ? rowscale[row0] : 0.f;
        float s1 = (row1 < M) ? rowscale[row1] : 0.f;
        #pragma unroll
        for (int nt = 0; nt < 4; nt++) {
            int col = warp_n * 32 + nt * 8 + tc * 2;
            if (row0 < M)
                *(__half2*)(C + (size_t)row0 * N + col) =
                    __floats2half2_rn(acc[mt][nt][0] * s0, acc[mt][nt][1] * s0);
            if (row1 < M)
                *(__half2*)(C + (size_t)row1 * N + col) =
                    __floats2half2_rn(acc[mt][nt][2] * s1, acc[mt][nt][3] * s1);
        }
    }
}

// ---------------- aggregation layer 1 (dim 256, fp16 in/out) + relu ----------------
__global__ void k_agg1_relu(const float* __restrict__ b1)
{
    int grp  = threadIdx.x >> 6;
    int lane = threadIdx.x & 63;
    int n = blockIdx.x * 4 + grp;
    if (n >= N_NODES) return;
    int beg = g_rowptr[n], end = g_rowptr[n + 1];

    float4 acc = make_float4(0.f, 0.f, 0.f, 0.f);
    int e = beg;
    #define LOAD4H(c) (*(const uint2*)(g_Z1h + (size_t)(c) * HID1 + (lane << 2)))
    #define ACC4H(u) do { \
        __half2 h0 = *reinterpret_cast<__half2*>(&(u).x); \
        __half2 h1 = *reinterpret_cast<__half2*>(&(u).y); \
        float2 f0 = __half22float2(h0); \
        float2 f1 = __half22float2(h1); \
        acc.x += f0.x; acc.y += f0.y; acc.z += f1.x; acc.w += f1.y; } while (0)
    for (; e + 4 <= end; e += 4) {
        int c0 = g_colidx[e], c1 = g_colidx[e + 1], c2 = g_colidx[e + 2], c3 = g_colidx[e + 3];
        uint2 u0 = LOAD4H(c0);
        uint2 u1 = LOAD4H(c1);
        uint2 u2 = LOAD4H(c2);
        uint2 u3 = LOAD4H(c3);
        ACC4H(u0); ACC4H(u1); ACC4H(u2); ACC4H(u3);
    }
    for (; e < end; e++) {
        int c = g_colidx[e];
        uint2 u = LOAD4H(c);
        ACC4H(u);
    }
    #undef LOAD4H
    #undef ACC4H
    float s = g_rsi[n];
    float4 bb = *(const float4*)(b1 + lane * 4);
    __half2 o0 = __floats2half2_rn(fmaxf(fmaf(s, acc.x, bb.x), 0.f),
                                   fmaxf(fmaf(s, acc.y, bb.y), 0.f));
    __half2 o1 = __floats2half2_rn(fmaxf(fmaf(s, acc.z, bb.z), 0.f),
                                   fmaxf(fmaf(s, acc.w, bb.w), 0.f));
    uint2 st;
    st.x = *reinterpret_cast<uint32_t*>(&o0);
    st.y = *reinterpret_cast<uint32_t*>(&o1);
    *(uint2*)(g_A1h + (size_t)n * HID1 + (lane << 2)) = st;
}

// ---------------- aggregation layer 2 (dim 64, fp16) + fused head ----------------
__global__ void k_agg2_head(const float* __restrict__ Wo2, const float* __restrict__ bo2,
                            float* __restrict__ out)
{
    int w    = threadIdx.x >> 5;
    int lane = threadIdx.x & 31;
    int n = blockIdx.x * 8 + w;
    if (n >= N_NODES) return;
    int beg = g_rowptr[n], end = g_rowptr[n + 1];

    float2 acc = make_float2(0.f, 0.f);
    int e = beg;
    for (; e + 4 <= end; e += 4) {
        int c0 = g_colidx[e], c1 = g_colidx[e + 1], c2 = g_colidx[e + 2], c3 = g_colidx[e + 3];
        float2 f0 = __half22float2(*(const __half2*)(g_Z2h + (size_t)c0 * ENDD + (lane << 1)));
        float2 f1 = __half22float2(*(const __half2*)(g_Z2h + (size_t)c1 * ENDD + (lane << 1)));
        float2 f2 = __half22float2(*(const __half2*)(g_Z2h + (size_t)c2 * ENDD + (lane << 1)));
        float2 f3 = __half22float2(*(const __half2*)(g_Z2h + (size_t)c3 * ENDD + (lane << 1)));
        acc.x += (f0.x + f1.x) + (f2.x + f3.x);
        acc.y += (f0.y + f1.y) + (f2.y + f3.y);
    }
    for (; e < end; e++) {
        int c = g_colidx[e];
        float2 f = __half22float2(*(const __half2*)(g_Z2h + (size_t)c * ENDD + (lane << 1)));
        acc.x += f.x; acc.y += f.y;
    }
    float s  = g_rsi[n];
    float t0 = fmaxf(fmaf(s, acc.x, g_bh[lane * 2 + 0]), 0.f);
    float t1 = fmaxf(fmaf(s, acc.y, g_bh[lane * 2 + 1]), 0.f);
    float p  = t0 * Wo2[lane * 2] + t1 * Wo2[lane * 2 + 1];
    #pragma unroll
    for (int off = 16; off; off >>= 1) p += __shfl_down_sync(0xffffffffu, p, off);
    if (lane == 0) out[n] = p + bo2[0];
}

// ---------------- launch ----------------
extern "C" void kernel_launch(void* const* d_in, const int* in_sizes, int n_in,
                              void* d_out, int out_size)
{
    const float* features = (const float*)d_in[0];   // [100000, 512]
    const int*   src      = (const int*)d_in[1];
    const int*   dst      = (const int*)d_in[2];
    const float* W1       = (const float*)d_in[3];   // [512, 256]
    const float* b1       = (const float*)d_in[4];
    const float* W2       = (const float*)d_in[5];   // [256, 128]
    const float* b2       = (const float*)d_in[6];
    const float* Wo1      = (const float*)d_in[7];   // [128, 64]
    const float* bo1      = (const float*)d_in[8];
    const float* Wo2      = (const float*)d_in[9];   // [64, 1]
    const float* bo2      = (const float*)d_in[10];
    float* out = (float*)d_out;

    const int nodeBlocks = (N_NODES + 255) / 256;    // 391
    const int edgeBlocks = (N_EDGES + 255) / 256;    // 12500
    const int zcBlocks   = (HID1 * IN_K + 255) / 256; // 512 (covers nodes too)

    float *rso;
    __half *z1, *a1, *z2;
    cudaGetSymbolAddress((void**)&rso, g_rso);
    cudaGetSymbolAddress((void**)&z1, g_Z1h);
    cudaGetSymbolAddress((void**)&a1, g_A1h);
    cudaGetSymbolAddress((void**)&z2, g_Z2h);

    // launches 1..3
    k_zero_cvt<<<zcBlocks, 256>>>(W1);
    k_degree<<<edgeBlocks, 256>>>(src, dst);
    k_rsqrt<<<nodeBlocks, 256>>>();

    // launch #4 (ncu-captured): layer-1 fp16 HMMA GEMM: Z1h = rso * (X @ W1)
    {
        dim3 grid(HID1 / 128, (N_NODES + 127) / 128);
        gemm1_h<<<grid, 256>>>(features, rso, z1);
    }

    // CSR build + weight folding
    k_scan1<<<nodeBlocks, 256>>>();
    k_scan2<<<1, 512>>>();
    k_scan3<<<nodeBlocks, 256>>>();
    k_fill<<<edgeBlocks, 256>>>(src, dst);
    k_fuse<<<HID1 + 1, ENDD>>>(W2, Wo1, b2, bo1);

    // A1h = relu(rsi * agg(Z1h) + b1)
    k_agg1_relu<<<N_NODES / 4, 256>>>(b1);

    // layer 2 (folded with head Linear1): Z2h = rso * (A1h @ (W2@Wo1))
    {
        dim3 grid(1, (N_NODES + 127) / 128);
        gemm2_h<<<grid, 256>>>(a1, rso, z2);
    }
    // out = relu(rsi * agg(Z2h) + bh) @ Wo2 + bo2
    k_agg2_head<<<N_NODES / 8, 256>>>(Wo2, bo2, out);
}

// round 6
// speedup vs baseline: 2.8454x; 1.1074x over previous
#include <cuda_runtime.h>
#include <cuda_fp16.h>
#include <cuda_bf16.h>
#include <cstdint>

#define N_NODES 100000
#define N_EDGES 3200000
#define IN_K    512     // IN_DIM * N_SEQ
#define HID1    256
#define HID2    128
#define ENDD    64

// ---------------- scratch (device globals; no allocation allowed) ----------------
__device__ int    g_deg_out[N_NODES];
__device__ int    g_deg_in[N_NODES];
__device__ int    g_fill[N_NODES];
__device__ float  g_rso[N_NODES];
__device__ float  g_rsi[N_NODES];
__device__ int    g_rowptr[N_NODES + 1];
__device__ int    g_bsums[512];
__device__ int    g_colidx[N_EDGES];
__device__ __half g_W1t[HID1 * IN_K];             // W1 transposed fp16 [n=256][k=512]
__device__ __half g_Z1h[(size_t)N_NODES * HID1];  // 51 MB  (L2-resident)
__device__ __half g_A1h[(size_t)N_NODES * HID1];  // 51 MB
__device__ __half g_Z2h[(size_t)N_NODES * ENDD];  // 12.8 MB
__device__ __half g_W2ft[ENDD * HID1];            // (W2@Wo1)^T fp16 [n=64][k=256]
__device__ float  g_bh[ENDD];                     // b2 @ Wo1 + bo1

// ---------------- preprocessing kernels ----------------
__global__ void k_zero_cvt(const float* __restrict__ W1)
{
    int i = blockIdx.x * blockDim.x + threadIdx.x;
    if (i < N_NODES) { g_deg_out[i] = 0; g_deg_in[i] = 0; g_fill[i] = 0; }
    if (i < HID1 * IN_K) {
        int n = i >> 9;
        int k = i & 511;
        g_W1t[i] = __float2half(W1[k * HID1 + n]);
    }
}

__global__ void k_degree(const int* __restrict__ src, const int* __restrict__ dst)
{
    int e = blockIdx.x * blockDim.x + threadIdx.x;
    if (e < N_EDGES) {
        atomicAdd(&g_deg_out[src[e]], 1);
        atomicAdd(&g_deg_in[dst[e]], 1);
    }
}

__global__ void k_rsqrt()
{
    int i = blockIdx.x * blockDim.x + threadIdx.x;
    if (i < N_NODES) {
        g_rso[i] = rsqrtf((float)max(g_deg_out[i], 1));
        g_rsi[i] = rsqrtf((float)max(g_deg_in[i], 1));
    }
}

__global__ void k_scan1()
{
    __shared__ int s[256];
    int t = threadIdx.x;
    int i = blockIdx.x * 256 + t;
    int v = (i < N_NODES) ? g_deg_in[i] : 0;
    s[t] = v; __syncthreads();
    #pragma unroll
    for (int off = 1; off < 256; off <<= 1) {
        int u = (t >= off) ? s[t - off] : 0;
        __syncthreads();
        s[t] += u;
        __syncthreads();
    }
    if (i < N_NODES) g_rowptr[i] = s[t] - v;
    if (t == 255) g_bsums[blockIdx.x] = s[255];
}

__global__ void k_scan2()
{
    __shared__ int s[512];
    const int nb = (N_NODES + 255) / 256;   // 391
    int t = threadIdx.x;
    int v = (t < nb) ? g_bsums[t] : 0;
    s[t] = v; __syncthreads();
    #pragma unroll
    for (int off = 1; off < 512; off <<= 1) {
        int u = (t >= off) ? s[t - off] : 0;
        __syncthreads();
        s[t] += u;
        __syncthreads();
    }
    if (t < nb) g_bsums[t] = s[t] - v;
}

__global__ void k_scan3()
{
    int i = blockIdx.x * blockDim.x + threadIdx.x;
    if (i < N_NODES) g_rowptr[i] += g_bsums[i >> 8];
    if (i == 0) g_rowptr[N_NODES] = N_EDGES;
}

__global__ void k_fill(const int* __restrict__ src, const int* __restrict__ dst)
{
    int e = blockIdx.x * blockDim.x + threadIdx.x;
    if (e < N_EDGES) {
        int d = dst[e];
        int p = g_rowptr[d] + atomicAdd(&g_fill[d], 1);
        g_colidx[p] = src[e];
    }
}

__global__ void k_fuse(const float* __restrict__ W2, const float* __restrict__ Wo1,
                       const float* __restrict__ b2, const float* __restrict__ bo1)
{
    int j = threadIdx.x;   // 0..63
    int k = blockIdx.x;    // 0..256
    if (k < HID1) {
        float s = 0.f;
        #pragma unroll 8
        for (int m = 0; m < HID2; m++) s += W2[k * HID2 + m] * Wo1[m * ENDD + j];
        g_W2ft[j * HID1 + k] = __float2half(s);
    } else {
        float s = bo1[j];
        #pragma unroll 8
        for (int m = 0; m < HID2; m++) s += b2[m] * Wo1[m * ENDD + j];
        g_bh[j] = s;
    }
}

// ---------------- fp16 HMMA helpers ----------------
__device__ __forceinline__ void mma_f16(float* c, uint32_t a0, uint32_t a1,
                                        uint32_t a2, uint32_t a3,
                                        uint32_t b0, uint32_t b1)
{
    asm volatile(
        "mma.sync.aligned.m16n8k16.row.col.f32.f16.f16.f32 "
        "{%0,%1,%2,%3}, {%4,%5,%6,%7}, {%8,%9}, {%0,%1,%2,%3};\n"
        : "+f"(c[0]), "+f"(c[1]), "+f"(c[2]), "+f"(c[3])
        : "r"(a0), "r"(a1), "r"(a2), "r"(a3), "r"(b0), "r"(b1));
}

__device__ __forceinline__ void ldsm_x4(uint32_t& r0, uint32_t& r1, uint32_t& r2,
                                        uint32_t& r3, uint32_t addr)
{
    asm volatile("ldmatrix.sync.aligned.m8n8.x4.shared.b16 {%0,%1,%2,%3}, [%4];"
                 : "=r"(r0), "=r"(r1), "=r"(r2), "=r"(r3) : "r"(addr));
}

#define HPITCH 40   // halves; 80B row pitch = 20 words -> LDSM conflict-free
#define STAGES 3

__device__ __forceinline__ uint32_t lds_h2(const __half* p)
{
    return *reinterpret_cast<const uint32_t*>(p);
}

// ---------------- GEMM1: Z1h = rso * (X @ W1), fp16 HMMA, 3-stage, ldmatrix ----
// X fp32 [100000,512] (register-staged cvt), W1t half [256][512].
// BM=128 BN=128 BK=32, 8 warps (2x4), warp tile 64x32.
__global__ void __launch_bounds__(256, 2)
gemm1_h(const float* __restrict__ A, const float* __restrict__ rowscale,
        __half* __restrict__ C)
{
    constexpr int M = N_NODES, N = HID1, K = IN_K;
    constexpr int NT = K / 32;   // 16
    constexpr int ASZ = 128 * HPITCH;   // halves per A stage

    extern __shared__ __half smh[];
    // As: [STAGES][128][HPITCH], Bs: [STAGES][128][HPITCH]
    __half* Asb = smh;
    __half* Bsb = smh + STAGES * ASZ;

    const int tid = threadIdx.x;
    const int lane = tid & 31;
    const int wid = tid >> 5;
    const int warp_m = wid >> 2;        // 0..1
    const int warp_n = wid & 3;         // 0..3
    const int g  = lane >> 2;
    const int tc = lane & 3;
    const int blockRow = blockIdx.y * 128;
    const int blockCol = blockIdx.x * 128;

    float acc[4][4][4];
    #pragma unroll
    for (int i = 0; i < 4; i++)
        #pragma unroll
        for (int j = 0; j < 4; j++)
            #pragma unroll
            for (int q = 0; q < 4; q++) acc[i][j][q] = 0.f;

    // A staging: 4 float4 per thread per tile
    int a_r[4], a_c[4];
    #pragma unroll
    for (int i = 0; i < 4; i++) {
        int slot = tid + i * 256;
        a_r[i] = slot >> 3;             // 0..127
        a_c[i] = (slot & 7) * 4;        // 0..28
    }
    // B: 2 cp.async 16B per thread per tile
    int b_n[2], b_c[2];
    #pragma unroll
    for (int i = 0; i < 2; i++) {
        int id = tid + i * 256;
        b_n[i] = id >> 2;               // 0..127
        b_c[i] = (id & 3) * 8;          // 0..24
    }

    // ldmatrix lane-address offsets
    const int a_ld_r = (lane & 7) + ((lane >> 3) & 1) * 8;  // row 0..15
    const int a_ld_c = (lane >> 4) * 8;                     // k 0/8
    const int b_ld_n = (lane & 7) + ((lane >> 4) & 1) * 8;  // n 0..15
    const int b_ld_c = ((lane >> 3) & 1) * 8;               // k 0/8

    float4 Areg[4];

    auto ldg_A = [&](int k0) {
        #pragma unroll
        for (int i = 0; i < 4; i++) {
            int grow = blockRow + a_r[i];
            Areg[i] = (grow < M) ? *(const float4*)(A + (size_t)grow * K + k0 + a_c[i])
                                 : make_float4(0.f, 0.f, 0.f, 0.f);
        }
    };
    auto sts_A = [&](int stage) {
        __half* asb = Asb + stage * ASZ;
        #pragma unroll
        for (int i = 0; i < 4; i++) {
            __half2 h0 = __floats2half2_rn(Areg[i].x, Areg[i].y);
            __half2 h1 = __floats2half2_rn(Areg[i].z, Areg[i].w);
            uint2 u;
            u.x = *reinterpret_cast<uint32_t*>(&h0);
            u.y = *reinterpret_cast<uint32_t*>(&h1);
            *(uint2*)&asb[a_r[i] * HPITCH + a_c[i]] = u;
        }
    };
    auto cp_B = [&](int stage, int k0) {
        __half* bsb = Bsb + stage * ASZ;
        #pragma unroll
        for (int i = 0; i < 2; i++) {
            uint32_t dst = (uint32_t)__cvta_generic_to_shared(&bsb[b_n[i] * HPITCH + b_c[i]]);
            const __half* srcp = g_W1t + (size_t)(blockCol + b_n[i]) * K + k0 + b_c[i];
            asm volatile("cp.async.cg.shared.global [%0], [%1], 16;\n"
                         :: "r"(dst), "l"(srcp));
        }
        asm volatile("cp.async.commit_group;\n");
    };

    // prologue: tile0 fully staged, tile1 B in flight + A in regs
    ldg_A(0);
    sts_A(0);
    cp_B(0, 0);
    ldg_A(32);
    cp_B(1, 32);

    for (int kt = 0; kt < NT; kt++) {
        if (kt + 1 < NT) asm volatile("cp.async.wait_group 1;\n");
        else             asm volatile("cp.async.wait_group 0;\n");
        __syncthreads();

        if (kt + 1 < NT) sts_A((kt + 1) % STAGES);                 // regs = tile kt+1
        if (kt + 2 < NT) { ldg_A((kt + 2) * 32); cp_B((kt + 2) % STAGES, (kt + 2) * 32); }

        const __half* asb = Asb + (kt % STAGES) * ASZ;
        const __half* bsb = Bsb + (kt % STAGES) * ASZ;

        #pragma unroll
        for (int ks = 0; ks < 2; ks++) {
            const int kb = ks * 16;
            uint32_t af[4][4];
            #pragma unroll
            for (int mt = 0; mt < 4; mt++) {
                int row = warp_m * 64 + mt * 16 + a_ld_r;
                uint32_t addr = (uint32_t)__cvta_generic_to_shared(
                    &asb[row * HPITCH + kb + a_ld_c]);
                ldsm_x4(af[mt][0], af[mt][1], af[mt][2], af[mt][3], addr);
            }
            uint32_t bf[4][2];
            #pragma unroll
            for (int h = 0; h < 2; h++) {
                int n = warp_n * 32 + h * 16 + b_ld_n;
                uint32_t addr = (uint32_t)__cvta_generic_to_shared(
                    &bsb[n * HPITCH + kb + b_ld_c]);
                ldsm_x4(bf[2 * h][0], bf[2 * h][1], bf[2 * h + 1][0], bf[2 * h + 1][1], addr);
            }
            #pragma unroll
            for (int mt = 0; mt < 4; mt++)
                #pragma unroll
                for (int nt = 0; nt < 4; nt++)
                    mma_f16(acc[mt][nt], af[mt][0], af[mt][1], af[mt][2], af[mt][3],
                            bf[nt][0], bf[nt][1]);
        }
    }

    // epilogue: rowscale + half2 store
    #pragma unroll
    for (int mt = 0; mt < 4; mt++) {
        int row0 = blockRow + warp_m * 64 + mt * 16 + g;
        int row1 = row0 + 8;
        float s0 = (row0 < M) ? rowscale[row0] : 0.f;
        float s1 = (row1 < M) ? rowscale[row1] : 0.f;
        #pragma unroll
        for (int nt = 0; nt < 4; nt++) {
            int col = blockCol + warp_n * 32 + nt * 8 + tc * 2;
            if (row0 < M)
                *(__half2*)(C + (size_t)row0 * N + col) =
                    __floats2half2_rn(acc[mt][nt][0] * s0, acc[mt][nt][1] * s0);
            if (row1 < M)
                *(__half2*)(C + (size_t)row1 * N + col) =
                    __floats2half2_rn(acc[mt][nt][2] * s1, acc[mt][nt][3] * s1);
        }
    }
}

// ---------------- GEMM2: Z2h = rso * (A1h @ W2f), fp16 HMMA ----------------
__global__ void __launch_bounds__(256, 2)
gemm2_h(const __half* __restrict__ A, const float* __restrict__ rowscale,
        __half* __restrict__ C)
{
    constexpr int M = N_NODES, N = ENDD, K = HID1;
    constexpr int NT = K / 32;   // 8

    __shared__ __half As[2][128][HPITCH];
    __shared__ __half Bs[2][64][HPITCH];

    const int tid = threadIdx.x;
    const int lane = tid & 31;
    const int wid = tid >> 5;
    const int warp_m = wid >> 1;        // 0..3
    const int warp_n = wid & 1;         // 0..1
    const int g  = lane >> 2;
    const int tc = lane & 3;
    const int blockRow = blockIdx.y * 128;

    float acc[2][4][4];
    #pragma unroll
    for (int i = 0; i < 2; i++)
        #pragma unroll
        for (int j = 0; j < 4; j++)
            #pragma unroll
            for (int q = 0; q < 4; q++) acc[i][j][q] = 0.f;

    int a_r[2], a_c[2];
    #pragma unroll
    for (int i = 0; i < 2; i++) {
        int id = tid + i * 256;
        a_r[i] = id >> 2;
        a_c[i] = (id & 3) * 8;
    }
    const int bn = tid >> 2;            // 0..63
    const int bc = (tid & 3) * 8;

    auto cp_AB = [&](int stage, int k0) {
        #pragma unroll
        for (int i = 0; i < 2; i++) {
            uint32_t dst = (uint32_t)__cvta_generic_to_shared(&As[stage][a_r[i]][a_c[i]]);
            const __half* srcp = A + (size_t)(blockRow + a_r[i]) * K + k0 + a_c[i];
            int sz = (blockRow + a_r[i] < M) ? 16 : 0;
            asm volatile("cp.async.cg.shared.global [%0], [%1], 16, %2;\n"
                         :: "r"(dst), "l"(srcp), "r"(sz));
        }
        {
            uint32_t dst = (uint32_t)__cvta_generic_to_shared(&Bs[stage][bn][bc]);
            const __half* srcp = g_W2ft + (size_t)bn * K + k0 + bc;
            asm volatile("cp.async.cg.shared.global [%0], [%1], 16;\n"
                         :: "r"(dst), "l"(srcp));
        }
        asm volatile("cp.async.commit_group;\n");
    };

    cp_AB(0, 0);

    for (int kt = 0; kt < NT; kt++) {
        asm volatile("cp.async.wait_group 0;\n");
        __syncthreads();
        if (kt + 1 < NT) cp_AB((kt + 1) & 1, (kt + 1) * 32);

        const int st = kt & 1;
        #pragma unroll
        for (int ks = 0; ks < 2; ks++) {
            const int kb = ks * 16;
            uint32_t af[2][4];
            #pragma unroll
            for (int mt = 0; mt < 2; mt++) {
                int row = warp_m * 32 + mt * 16 + g;
                af[mt][0] = lds_h2(&As[st][row    ][kb + 2 * tc    ]);
                af[mt][1] = lds_h2(&As[st][row + 8][kb + 2 * tc    ]);
                af[mt][2] = lds_h2(&As[st][row    ][kb + 2 * tc + 8]);
                af[mt][3] = lds_h2(&As[st][row + 8][kb + 2 * tc + 8]);
            }
            uint32_t bf[4][2];
            #pragma unroll
            for (int nt = 0; nt < 4; nt++) {
                int n = warp_n * 32 + nt * 8 + g;
                bf[nt][0] = lds_h2(&Bs[st][n][kb + 2 * tc    ]);
                bf[nt][1] = lds_h2(&Bs[st][n][kb + 2 * tc + 8]);
            }
            #pragma unroll
            for (int mt = 0; mt < 2; mt++)
                #pragma unroll
                for (int nt = 0; nt < 4; nt++)
                    mma_f16(acc[mt][nt], af[mt][0], af[mt][1], af[mt][2], af[mt][3],
                            bf[nt][0], bf[nt][1]);
        }
    }

    #pragma unroll
    for (int mt = 0; mt < 2; mt++) {
        int row0 = blockRow + warp_m * 32 + mt * 16 + g;
        int row1 = row0 + 8;
        float s0 = (row0 < M) ? rowscale[row0] : 0.f;
        float s1 = (row1 < M) ? rowscale[row1] : 0.f;
        #pragma unroll
        for (int nt = 0; nt < 4; nt++) {
            int col = warp_n * 32 + nt * 8 + tc * 2;
            if (row0 < M)
                *(__half2*)(C + (size_t)row0 * N + col) =
                    __floats2half2_rn(acc[mt][nt][0] * s0, acc[mt][nt][1] * s0);
            if (row1 < M)
                *(__half2*)(C + (size_t)row1 * N + col) =
                    __floats2half2_rn(acc[mt][nt][2] * s1, acc[mt][nt][3] * s1);
        }
    }
}

// ---------------- aggregation layer 1 (dim 256, fp16) + relu ----------------
// 1 warp per node; lane owns 8 halves (uint4); 4-edge unroll for MLP
__global__ void k_agg1_relu(const float* __restrict__ b1)
{
    int w    = threadIdx.x >> 5;
    int lane = threadIdx.x & 31;
    int n = blockIdx.x * 8 + w;
    if (n >= N_NODES) return;
    int beg = g_rowptr[n], end = g_rowptr[n + 1];

    float acc[8];
    #pragma unroll
    for (int i = 0; i < 8; i++) acc[i] = 0.f;

    const __half* basep = g_Z1h + (lane << 3);

    #define ACC8(u) do { \
        float2 f0 = __half22float2(*reinterpret_cast<__half2*>(&(u).x)); \
        float2 f1 = __half22float2(*reinterpret_cast<__half2*>(&(u).y)); \
        float2 f2 = __half22float2(*reinterpret_cast<__half2*>(&(u).z)); \
        float2 f3 = __half22float2(*reinterpret_cast<__half2*>(&(u).w)); \
        acc[0] += f0.x; acc[1] += f0.y; acc[2] += f1.x; acc[3] += f1.y; \
        acc[4] += f2.x; acc[5] += f2.y; acc[6] += f3.x; acc[7] += f3.y; } while (0)

    int e = beg;
    for (; e + 4 <= end; e += 4) {
        int c0 = g_colidx[e], c1 = g_colidx[e + 1], c2 = g_colidx[e + 2], c3 = g_colidx[e + 3];
        uint4 u0 = *(const uint4*)(basep + (size_t)c0 * HID1);
        uint4 u1 = *(const uint4*)(basep + (size_t)c1 * HID1);
        uint4 u2 = *(const uint4*)(basep + (size_t)c2 * HID1);
        uint4 u3 = *(const uint4*)(basep + (size_t)c3 * HID1);
        ACC8(u0); ACC8(u1); ACC8(u2); ACC8(u3);
    }
    for (; e < end; e++) {
        int c = g_colidx[e];
        uint4 u = *(const uint4*)(basep + (size_t)c * HID1);
        ACC8(u);
    }
    #undef ACC8

    float s = g_rsi[n];
    float4 bb0 = *(const float4*)(b1 + lane * 8);
    float4 bb1 = *(const float4*)(b1 + lane * 8 + 4);
    __half2 o0 = __floats2half2_rn(fmaxf(fmaf(s, acc[0], bb0.x), 0.f),
                                   fmaxf(fmaf(s, acc[1], bb0.y), 0.f));
    __half2 o1 = __floats2half2_rn(fmaxf(fmaf(s, acc[2], bb0.z), 0.f),
                                   fmaxf(fmaf(s, acc[3], bb0.w), 0.f));
    __half2 o2 = __floats2half2_rn(fmaxf(fmaf(s, acc[4], bb1.x), 0.f),
                                   fmaxf(fmaf(s, acc[5], bb1.y), 0.f));
    __half2 o3 = __floats2half2_rn(fmaxf(fmaf(s, acc[6], bb1.z), 0.f),
                                   fmaxf(fmaf(s, acc[7], bb1.w), 0.f));
    uint4 st;
    st.x = *reinterpret_cast<uint32_t*>(&o0);
    st.y = *reinterpret_cast<uint32_t*>(&o1);
    st.z = *reinterpret_cast<uint32_t*>(&o2);
    st.w = *reinterpret_cast<uint32_t*>(&o3);
    *(uint4*)(g_A1h + (size_t)n * HID1 + (lane << 3)) = st;
}

// ---------------- aggregation layer 2 (dim 64, fp16) + fused head ----------------
__global__ void k_agg2_head(const float* __restrict__ Wo2, const float* __restrict__ bo2,
                            float* __restrict__ out)
{
    int w    = threadIdx.x >> 5;
    int lane = threadIdx.x & 31;
    int n = blockIdx.x * 8 + w;
    if (n >= N_NODES) return;
    int beg = g_rowptr[n], end = g_rowptr[n + 1];

    float2 acc = make_float2(0.f, 0.f);
    int e = beg;
    for (; e + 4 <= end; e += 4) {
        int c0 = g_colidx[e], c1 = g_colidx[e + 1], c2 = g_colidx[e + 2], c3 = g_colidx[e + 3];
        float2 f0 = __half22float2(*(const __half2*)(g_Z2h + (size_t)c0 * ENDD + (lane << 1)));
        float2 f1 = __half22float2(*(const __half2*)(g_Z2h + (size_t)c1 * ENDD + (lane << 1)));
        float2 f2 = __half22float2(*(const __half2*)(g_Z2h + (size_t)c2 * ENDD + (lane << 1)));
        float2 f3 = __half22float2(*(const __half2*)(g_Z2h + (size_t)c3 * ENDD + (lane << 1)));
        acc.x += (f0.x + f1.x) + (f2.x + f3.x);
        acc.y += (f0.y + f1.y) + (f2.y + f3.y);
    }
    for (; e < end; e++) {
        int c = g_colidx[e];
        float2 f = __half22float2(*(const __half2*)(g_Z2h + (size_t)c * ENDD + (lane << 1)));
        acc.x += f.x; acc.y += f.y;
    }
    float s  = g_rsi[n];
    float t0 = fmaxf(fmaf(s, acc.x, g_bh[lane * 2 + 0]), 0.f);
    float t1 = fmaxf(fmaf(s, acc.y, g_bh[lane * 2 + 1]), 0.f);
    float p  = t0 * Wo2[lane * 2] + t1 * Wo2[lane * 2 + 1];
    #pragma unroll
    for (int off = 16; off; off >>= 1) p += __shfl_down_sync(0xffffffffu, p, off);
    if (lane == 0) out[n] = p + bo2[0];
}

// ---------------- launch ----------------
extern "C" void kernel_launch(void* const* d_in, const int* in_sizes, int n_in,
                              void* d_out, int out_size)
{
    const float* features = (const float*)d_in[0];
    const int*   src      = (const int*)d_in[1];
    const int*   dst      = (const int*)d_in[2];
    const float* W1       = (const float*)d_in[3];
    const float* b1       = (const float*)d_in[4];
    const float* W2       = (const float*)d_in[5];
    const float* b2       = (const float*)d_in[6];
    const float* Wo1      = (const float*)d_in[7];
    const float* bo1      = (const float*)d_in[8];
    const float* Wo2      = (const float*)d_in[9];
    const float* bo2      = (const float*)d_in[10];
    float* out = (float*)d_out;

    const int nodeBlocks = (N_NODES + 255) / 256;     // 391
    const int edgeBlocks = (N_EDGES + 255) / 256;     // 12500
    const int zcBlocks   = (HID1 * IN_K + 255) / 256; // 512
    const int GEMM1_SMEM = 2 * STAGES * 128 * HPITCH * (int)sizeof(__half);  // 61440

    cudaFuncSetAttribute(gemm1_h, cudaFuncAttributeMaxDynamicSharedMemorySize,
                         GEMM1_SMEM);

    float *rso;
    __half *z1, *a1, *z2;
    cudaGetSymbolAddress((void**)&rso, g_rso);
    cudaGetSymbolAddress((void**)&z1, g_Z1h);
    cudaGetSymbolAddress((void**)&a1, g_A1h);
    cudaGetSymbolAddress((void**)&z2, g_Z2h);

    // launches 1..3
    k_zero_cvt<<<zcBlocks, 256>>>(W1);
    k_degree<<<edgeBlocks, 256>>>(src, dst);
    k_rsqrt<<<nodeBlocks, 256>>>();

    // launch #4 (ncu-captured): layer-1 fp16 HMMA GEMM
    {
        dim3 grid(HID1 / 128, (N_NODES + 127) / 128);
        gemm1_h<<<grid, 256, GEMM1_SMEM>>>(features, rso, z1);
    }

    // CSR build + weight folding
    k_scan1<<<nodeBlocks, 256>>>();
    k_scan2<<<1, 512>>>();
    k_scan3<<<nodeBlocks, 256>>>();
    k_fill<<<edgeBlocks, 256>>>(src, dst);
    k_fuse<<<HID1 + 1, ENDD>>>(W2, Wo1, b2, bo1);

    // A1h = relu(rsi * agg(Z1h) + b1)
    k_agg1_relu<<<(N_NODES + 7) / 8, 256>>>(b1);

    // layer 2 (folded): Z2h = rso * (A1h @ (W2@Wo1))
    {
        dim3 grid(1, (N_NODES + 127) / 128);
        gemm2_h<<<grid, 256>>>(a1, rso, z2);
    }
    // out = relu(rsi * agg(Z2h) + bh) @ Wo2 + bo2
    k_agg2_head<<<(N_NODES + 7) / 8, 256>>>(Wo2, bo2, out);
}